// round 9
// baseline (speedup 1.0000x reference)
#include <cuda_runtime.h>
#include <math.h>
#include <stdint.h>

// Fixed shapes: x[131072,512] f32, clusters[64,512] f32, alpha scalar
#define DDIM 512
#define KDIM 64
#define TILE_ROWS 256
#define KC 16                    // k elements per cp.async chunk
#define NCH (DDIM / KC)          // 32 chunks
#define THREADS 256
#define APITCH 80                // bytes per A row in smem (16 floats + 4 pad)
#define ASTAGE (TILE_ROWS * APITCH)  // 20480 B

// SMEM layout (bytes)
#define SM_B    0                          // 64 ksteps * 256 float2 = 131072 B
#define SM_A    131072                     // 4 stages * 20480 = 81920 B
#define SM_WRED 212992                     // 8 floats
#define SMEM_TOTAL 213120

#define MAXBLK 8192
__device__ float g_cn[KDIM * DDIM];        // normalized clusters [k][d]
__device__ float g_partial[MAXBLK];        // per-block loss partials

// ---- helpers ---------------------------------------------------------------
static __device__ __forceinline__ uint32_t smem_u32(const void* p) {
    uint32_t a;
    asm("{ .reg .u64 t; cvta.to.shared.u64 t, %1; cvt.u32.u64 %0, t; }"
        : "=r"(a) : "l"(p));
    return a;
}
static __device__ __forceinline__ void cp16(uint32_t saddr, const void* g) {
    asm volatile("cp.async.cg.shared.global [%0], [%1], 16;" :: "r"(saddr), "l"(g));
}
#define CP_COMMIT() asm volatile("cp.async.commit_group;" ::: "memory")
#define CP_WAIT2()  asm volatile("cp.async.wait_group 2;" ::: "memory")

// 3xTF32 split: hi = round-to-nearest tf32 (exact f32 value), lo = residual.
static __device__ __forceinline__ void split_tf32(float v, uint32_t& hi, uint32_t& lo) {
    asm("cvt.rna.tf32.f32 %0, %1;" : "=r"(hi) : "f"(v));
    lo = __float_as_uint(v - __uint_as_float(hi));
}

static __device__ __forceinline__ void mma_tf32(float* c,
                                                uint32_t a0, uint32_t a1,
                                                uint32_t a2, uint32_t a3,
                                                uint32_t b0, uint32_t b1) {
    asm volatile(
        "mma.sync.aligned.m16n8k8.row.col.f32.tf32.tf32.f32 "
        "{%0,%1,%2,%3}, {%4,%5,%6,%7}, {%8,%9}, {%0,%1,%2,%3};"
        : "+f"(c[0]), "+f"(c[1]), "+f"(c[2]), "+f"(c[3])
        : "r"(a0), "r"(a1), "r"(a2), "r"(a3), "r"(b0), "r"(b1));
}

// ---------------------------------------------------------------------------
// Kernel 1: L2-normalize clusters -> g_cn[k][d]
// ---------------------------------------------------------------------------
__global__ void norm_clusters_kernel(const float* __restrict__ clusters) {
    int k = blockIdx.x;          // 64 blocks
    int t = threadIdx.x;         // 128 threads
    float4 v = ((const float4*)(clusters + (size_t)k * DDIM))[t];
    float ss = v.x * v.x + v.y * v.y + v.z * v.z + v.w * v.w;
    #pragma unroll
    for (int o = 16; o; o >>= 1) ss += __shfl_xor_sync(0xffffffffu, ss, o);
    __shared__ float ws[4];
    __shared__ float s_inv;
    if ((t & 31) == 0) ws[t >> 5] = ss;
    __syncthreads();
    if (t == 0) {
        float s = ws[0] + ws[1] + ws[2] + ws[3];
        s_inv = 1.0f / fmaxf(sqrtf(s), 1e-12f);
    }
    __syncthreads();
    float iv = s_inv;
    float4* o4 = (float4*)(g_cn + (size_t)k * DDIM);
    o4[t] = make_float4(v.x * iv, v.y * iv, v.z * iv, v.w * iv);
}

// ---------------------------------------------------------------------------
// Kernel 2: 3xTF32 mma.sync GEMM tile 256x64 + fused normalize/softmax/loss
// Warp w owns rows w*32..w*32+31 (2 x m16 tiles) x all 64 cols (8 x n8 tiles).
// ---------------------------------------------------------------------------
__global__ __launch_bounds__(THREADS, 1)
void cluster_mma_kernel(const float* __restrict__ x,
                        const float* __restrict__ alphap,
                        float* __restrict__ out,
                        int loss_off, int store_probs) {
    extern __shared__ char smem[];
    const uint32_t sb = smem_u32(smem);
    const int t = threadIdx.x;
    const int w = t >> 5, lane = t & 31;
    const int g = lane >> 2, tg = lane & 3;
    const size_t row0 = (size_t)blockIdx.x * TILE_ROWS;

    // ---- build B fragments in smem (mma B-frag layout, plain f32 pairs) ----
    // BP[kk][j*32 + lane] = { cn[n][kk*8+tg], cn[n][kk*8+tg+4] }, n = j*8 + (lane>>2)
    {
        float2* bp = (float2*)smem;
        #pragma unroll 4
        for (int i = 0; i < 64; ++i) {
            int idx = t + THREADS * i;        // 0..16383
            int kk = idx >> 8;
            int s  = idx & 255;
            int n  = s >> 2, tt = s & 3;
            const float* c = g_cn + (size_t)n * DDIM + kk * 8 + tt;
            bp[idx] = make_float2(c[0], c[4]);
        }
    }

    // ---- prologue: prefetch chunks 0..2 ----
    const float* xrow = x + (row0 + t) * DDIM;
    #pragma unroll
    for (int pc = 0; pc < 3; ++pc) {
        uint32_t ab = sb + SM_A + pc * ASTAGE + t * APITCH;
        const float* src = xrow + pc * KC;
        #pragma unroll
        for (int q = 0; q < 4; ++q) cp16(ab + q * 16, src + q * 4);
        CP_COMMIT();
    }

    float acc[2][8][4];
    #pragma unroll
    for (int m = 0; m < 2; ++m)
        #pragma unroll
        for (int j = 0; j < 8; ++j)
            #pragma unroll
            for (int r = 0; r < 4; ++r) acc[m][j][r] = 0.f;
    float ssq[4] = {0.f, 0.f, 0.f, 0.f};

    // ---- mainloop ----
    for (int c = 0; c < NCH; ++c) {
        CP_WAIT2();                 // chunk c landed
        __syncthreads();            // visible to all warps; stage (c-1)&3 free
        const int st = c & 3;

        // prefetch chunk c+3 into stage (c+3)&3
        if (c + 3 < NCH) {
            uint32_t ab = sb + SM_A + ((c + 3) & 3) * ASTAGE + t * APITCH;
            const float* src = xrow + (c + 3) * KC;
            #pragma unroll
            for (int q = 0; q < 4; ++q) cp16(ab + q * 16, src + q * 4);
        }
        CP_COMMIT();

        const char* ap = smem + SM_A + st * ASTAGE;

        // row sum-of-squares from this chunk (exact fp32)
        #pragma unroll
        for (int i = 0; i < 4; ++i) {
            float4 v = *(const float4*)(ap + (w * 32 + i * 8 + g) * APITCH + tg * 16);
            ssq[i] += v.x * v.x + v.y * v.y + v.z * v.z + v.w * v.w;
        }

        // 2 k-steps of 8, 3xTF32 compensated
        #pragma unroll
        for (int u = 0; u < 2; ++u) {
            const int kk = c * 2 + u;
            const float2* bp = (const float2*)smem + kk * 256 + lane;
            uint32_t bh[8][2], bl[8][2];
            #pragma unroll
            for (int j = 0; j < 8; ++j) {
                float2 b = bp[j * 32];
                split_tf32(b.x, bh[j][0], bl[j][0]);
                split_tf32(b.y, bh[j][1], bl[j][1]);
            }

            const char* abase = ap + (w * 32 + g) * APITCH + u * 32 + tg * 4;
            #pragma unroll
            for (int m = 0; m < 2; ++m) {
                const char* am = abase + m * (16 * APITCH);
                float a0 = *(const float*)(am);
                float a1 = *(const float*)(am + 8 * APITCH);
                float a2 = *(const float*)(am + 16);
                float a3 = *(const float*)(am + 8 * APITCH + 16);
                uint32_t ah[4], al[4];
                split_tf32(a0, ah[0], al[0]);
                split_tf32(a1, ah[1], al[1]);
                split_tf32(a2, ah[2], al[2]);
                split_tf32(a3, ah[3], al[3]);
                #pragma unroll
                for (int j = 0; j < 8; ++j) {
                    mma_tf32(acc[m][j], ah[0], ah[1], ah[2], ah[3],
                             bh[j][0], bh[j][1]);
                    mma_tf32(acc[m][j], ah[0], ah[1], ah[2], ah[3],
                             bl[j][0], bl[j][1]);
                    mma_tf32(acc[m][j], al[0], al[1], al[2], al[3],
                             bh[j][0], bh[j][1]);
                }
            }
        }
    }

    // ---- finalize norms: reduce over the 4 quad lanes ----
    #pragma unroll
    for (int i = 0; i < 4; ++i) {
        ssq[i] += __shfl_xor_sync(0xffffffffu, ssq[i], 1);
        ssq[i] += __shfl_xor_sync(0xffffffffu, ssq[i], 2);
    }

    const float alphav = *alphap;
    float lossacc = 0.f;

    // ---- epilogue: per-row scale, softmax over 64 (quad-shfl), store, loss ----
    #pragma unroll
    for (int i = 0; i < 4; ++i) {      // row R = row0 + w*32 + i*8 + g
        const int m = i >> 1, hi = i & 1;
        float inv = 1.0f / fmaxf(sqrtf(ssq[i]), 1e-12f);
        float s[16];
        #pragma unroll
        for (int j = 0; j < 8; ++j) {
            s[2 * j]     = acc[m][j][hi * 2]     * inv;
            s[2 * j + 1] = acc[m][j][hi * 2 + 1] * inv;
        }
        float mx = -1e30f;
        #pragma unroll
        for (int j = 0; j < 16; ++j) mx = fmaxf(mx, s[j] * alphav);
        mx = fmaxf(mx, __shfl_xor_sync(0xffffffffu, mx, 1));
        mx = fmaxf(mx, __shfl_xor_sync(0xffffffffu, mx, 2));
        float e[16];
        float es = 0.f, ps = 0.f;
        #pragma unroll
        for (int j = 0; j < 16; ++j) {
            e[j] = __expf(s[j] * alphav - mx);
            es += e[j];
            ps += e[j] * s[j];
        }
        es += __shfl_xor_sync(0xffffffffu, es, 1);
        es += __shfl_xor_sync(0xffffffffu, es, 2);
        ps += __shfl_xor_sync(0xffffffffu, ps, 1);
        ps += __shfl_xor_sync(0xffffffffu, ps, 2);
        float rs = 1.0f / es;
        if (tg == 0) lossacc += ps * rs;
        if (store_probs) {
            size_t R = row0 + (size_t)w * 32 + i * 8 + g;
            float* ob = out + (size_t)loss_off + R * KDIM + tg * 2;
            #pragma unroll
            for (int j = 0; j < 8; ++j) {   // scalar: out may be 4B-misaligned by loss_off
                ob[j * 8]     = e[2 * j] * rs;
                ob[j * 8 + 1] = e[2 * j + 1] * rs;
            }
        }
    }

    // ---- deterministic per-block loss partial ----
    #pragma unroll
    for (int o = 16; o; o >>= 1) lossacc += __shfl_xor_sync(0xffffffffu, lossacc, o);
    float* wred = (float*)(smem + SM_WRED);
    if (lane == 0) wred[w] = lossacc;
    __syncthreads();
    if (t == 0) {
        float ssum = 0.f;
        #pragma unroll
        for (int i = 0; i < 8; ++i) ssum += wred[i];
        g_partial[blockIdx.x] = ssum;
    }
}

// ---------------------------------------------------------------------------
// Kernel 3: deterministic loss finalize
// ---------------------------------------------------------------------------
__global__ void finalize_kernel(float* __restrict__ out, int nblocks, int N,
                                int write_loss) {
    if (!write_loss) return;
    __shared__ float sm[256];
    float s = 0.f;
    for (int i = threadIdx.x; i < nblocks; i += 256) s += g_partial[i];
    sm[threadIdx.x] = s;
    __syncthreads();
    for (int o = 128; o; o >>= 1) {
        if (threadIdx.x < o) sm[threadIdx.x] += sm[threadIdx.x + o];
        __syncthreads();
    }
    if (threadIdx.x == 0) out[0] = -sm[0] / (float)N;
}

// ---------------------------------------------------------------------------
extern "C" void kernel_launch(void* const* d_in, const int* in_sizes, int n_in,
                              void* d_out, int out_size) {
    const float* x        = (const float*)d_in[0];
    const float* clusters = (const float*)d_in[1];
    const float* alpha    = (const float*)d_in[2];
    float* out = (float*)d_out;

    int N = in_sizes[0] / DDIM;              // 131072
    int nblocks = N / TILE_ROWS;             // 512

    // Output layout (confirmed R5): out[0]=loss, out[1:]=probs when size nk+1
    long long nk = (long long)N * KDIM;
    int loss_off = 0, store_probs = 1, write_loss = 0;
    if ((long long)out_size == nk + 1) { loss_off = 1; write_loss = 1; }
    else if ((long long)out_size == nk) { loss_off = 0; write_loss = 0; }
    else { store_probs = 0; write_loss = 1; }

    cudaFuncSetAttribute(cluster_mma_kernel,
                         cudaFuncAttributeMaxDynamicSharedMemorySize, SMEM_TOTAL);

    norm_clusters_kernel<<<KDIM, 128>>>(clusters);
    cluster_mma_kernel<<<nblocks, THREADS, SMEM_TOTAL>>>(x, alpha, out,
                                                         loss_off, store_probs);
    finalize_kernel<<<1, 256>>>(out, nblocks, N, write_loss);
}

// round 10
// speedup vs baseline: 1.4978x; 1.4978x over previous
#include <cuda_runtime.h>
#include <math.h>
#include <stdint.h>

// Fixed shapes: x[131072,512] f32, clusters[64,512] f32, alpha scalar
#define DDIM 512
#define KDIM 64
#define TILE_ROWS 256
#define KC 16                    // k elements per cp.async chunk
#define NCH (DDIM / KC)          // 32 chunks
#define THREADS 256
#define APITCH 80                // bytes per A row in smem (16 floats + 4 pad)
#define ASTAGE (TILE_ROWS * APITCH)  // 20480 B

// SMEM layout (bytes)
#define SM_B    0                          // 64 ksteps * 256 float2 = 131072 B
#define SM_A    131072                     // 4 stages * 20480 = 81920 B
#define SM_WRED 212992                     // 8 floats
#define SMEM_TOTAL 213120

#define MAXBLK 8192
__device__ float g_cn[KDIM * DDIM];        // normalized clusters [k][d], RNA-rounded to tf32
__device__ float g_partial[MAXBLK];        // per-block loss partials

// ---- helpers ---------------------------------------------------------------
static __device__ __forceinline__ uint32_t smem_u32(const void* p) {
    uint32_t a;
    asm("{ .reg .u64 t; cvta.to.shared.u64 t, %1; cvt.u32.u64 %0, t; }"
        : "=r"(a) : "l"(p));
    return a;
}
static __device__ __forceinline__ void cp16(uint32_t saddr, const void* g) {
    asm volatile("cp.async.cg.shared.global [%0], [%1], 16;" :: "r"(saddr), "l"(g));
}
#define CP_COMMIT() asm volatile("cp.async.commit_group;" ::: "memory")
#define CP_WAIT2()  asm volatile("cp.async.wait_group 2;" ::: "memory")

// Round-to-nearest tf32 (result is an f32 bit pattern with low mantissa zeroed).
static __device__ __forceinline__ uint32_t rna_tf32(float v) {
    uint32_t r;
    asm("cvt.rna.tf32.f32 %0, %1;" : "=r"(r) : "f"(v));
    return r;
}

static __device__ __forceinline__ void mma_tf32(float* c,
                                                uint32_t a0, uint32_t a1,
                                                uint32_t a2, uint32_t a3,
                                                uint32_t b0, uint32_t b1) {
    asm volatile(
        "mma.sync.aligned.m16n8k8.row.col.f32.tf32.tf32.f32 "
        "{%0,%1,%2,%3}, {%4,%5,%6,%7}, {%8,%9}, {%0,%1,%2,%3};"
        : "+f"(c[0]), "+f"(c[1]), "+f"(c[2]), "+f"(c[3])
        : "r"(a0), "r"(a1), "r"(a2), "r"(a3), "r"(b0), "r"(b1));
}

// ---------------------------------------------------------------------------
// Kernel 1: L2-normalize clusters -> g_cn[k][d], RNA-rounded to tf32 values
// (B operand then needs NO in-loop conversion; bias-free truncation.)
// ---------------------------------------------------------------------------
__global__ void norm_clusters_kernel(const float* __restrict__ clusters) {
    int k = blockIdx.x;          // 64 blocks
    int t = threadIdx.x;         // 128 threads
    float4 v = ((const float4*)(clusters + (size_t)k * DDIM))[t];
    float ss = v.x * v.x + v.y * v.y + v.z * v.z + v.w * v.w;
    #pragma unroll
    for (int o = 16; o; o >>= 1) ss += __shfl_xor_sync(0xffffffffu, ss, o);
    __shared__ float ws[4];
    __shared__ float s_inv;
    if ((t & 31) == 0) ws[t >> 5] = ss;
    __syncthreads();
    if (t == 0) {
        float s = ws[0] + ws[1] + ws[2] + ws[3];
        s_inv = 1.0f / fmaxf(sqrtf(s), 1e-12f);
    }
    __syncthreads();
    float iv = s_inv;
    uint4 r;
    r.x = rna_tf32(v.x * iv);
    r.y = rna_tf32(v.y * iv);
    r.z = rna_tf32(v.z * iv);
    r.w = rna_tf32(v.w * iv);
    ((uint4*)(g_cn + (size_t)k * DDIM))[t] = r;
}

// ---------------------------------------------------------------------------
// Kernel 2: tf32(RNA) mma.sync GEMM tile 256x64 + fused normalize/softmax/loss
// Warp w owns rows w*32..w*32+31 (2 x m16 tiles) x all 64 cols (8 x n8 tiles).
// ---------------------------------------------------------------------------
__global__ __launch_bounds__(THREADS, 1)
void cluster_mma_kernel(const float* __restrict__ x,
                        const float* __restrict__ alphap,
                        float* __restrict__ out,
                        int loss_off, int store_probs) {
    extern __shared__ char smem[];
    const uint32_t sb = smem_u32(smem);
    const int t = threadIdx.x;
    const int w = t >> 5, lane = t & 31;
    const int g = lane >> 2, tg = lane & 3;
    const size_t row0 = (size_t)blockIdx.x * TILE_ROWS;

    // ---- build B fragments in smem (mma B-frag layout; values already tf32) ----
    // BP[kk][j*32 + lane] = { cn[n][kk*8+tg], cn[n][kk*8+tg+4] }, n = j*8 + (lane>>2)
    {
        float2* bp = (float2*)smem;
        #pragma unroll 4
        for (int i = 0; i < 64; ++i) {
            int idx = t + THREADS * i;        // 0..16383
            int kk = idx >> 8;
            int s  = idx & 255;
            int n  = s >> 2, tt = s & 3;
            const float* c = g_cn + (size_t)n * DDIM + kk * 8 + tt;
            bp[idx] = make_float2(c[0], c[4]);
        }
    }

    // ---- prologue: prefetch chunks 0..2 ----
    const float* xrow = x + (row0 + t) * DDIM;
    #pragma unroll
    for (int pc = 0; pc < 3; ++pc) {
        uint32_t ab = sb + SM_A + pc * ASTAGE + t * APITCH;
        const float* src = xrow + pc * KC;
        #pragma unroll
        for (int q = 0; q < 4; ++q) cp16(ab + q * 16, src + q * 4);
        CP_COMMIT();
    }

    float acc[2][8][4];
    #pragma unroll
    for (int m = 0; m < 2; ++m)
        #pragma unroll
        for (int j = 0; j < 8; ++j)
            #pragma unroll
            for (int r = 0; r < 4; ++r) acc[m][j][r] = 0.f;
    float ssq[4] = {0.f, 0.f, 0.f, 0.f};

    // ---- mainloop ----
    for (int c = 0; c < NCH; ++c) {
        CP_WAIT2();                 // chunk c landed
        __syncthreads();            // visible to all warps; stage (c-1)&3 free
        const int st = c & 3;

        // prefetch chunk c+3 into stage (c+3)&3
        if (c + 3 < NCH) {
            uint32_t ab = sb + SM_A + ((c + 3) & 3) * ASTAGE + t * APITCH;
            const float* src = xrow + (c + 3) * KC;
            #pragma unroll
            for (int q = 0; q < 4; ++q) cp16(ab + q * 16, src + q * 4);
        }
        CP_COMMIT();

        const char* ap = smem + SM_A + st * ASTAGE;

        // row sum-of-squares from this chunk (exact fp32, pre-rounding)
        #pragma unroll
        for (int i = 0; i < 4; ++i) {
            float4 v = *(const float4*)(ap + (w * 32 + i * 8 + g) * APITCH + tg * 16);
            ssq[i] += v.x * v.x + v.y * v.y + v.z * v.z + v.w * v.w;
        }

        // 2 k-steps of 8, single MMA per (m,j); A RNA-rounded in-register
        #pragma unroll
        for (int u = 0; u < 2; ++u) {
            const int kk = c * 2 + u;
            const float2* bp = (const float2*)smem + kk * 256 + lane;
            uint2 b[8];
            #pragma unroll
            for (int j = 0; j < 8; ++j) b[j] = *(const uint2*)(bp + j * 32);

            const char* abase = ap + (w * 32 + g) * APITCH + u * 32 + tg * 4;
            #pragma unroll
            for (int m = 0; m < 2; ++m) {
                const char* am = abase + m * (16 * APITCH);
                uint32_t a0 = rna_tf32(*(const float*)(am));
                uint32_t a1 = rna_tf32(*(const float*)(am + 8 * APITCH));
                uint32_t a2 = rna_tf32(*(const float*)(am + 16));
                uint32_t a3 = rna_tf32(*(const float*)(am + 8 * APITCH + 16));
                #pragma unroll
                for (int j = 0; j < 8; ++j)
                    mma_tf32(acc[m][j], a0, a1, a2, a3, b[j].x, b[j].y);
            }
        }
    }

    // ---- finalize norms: reduce over the 4 quad lanes ----
    #pragma unroll
    for (int i = 0; i < 4; ++i) {
        ssq[i] += __shfl_xor_sync(0xffffffffu, ssq[i], 1);
        ssq[i] += __shfl_xor_sync(0xffffffffu, ssq[i], 2);
    }

    const float alphav = *alphap;
    float lossacc = 0.f;

    // ---- epilogue: per-row scale, softmax over 64 (quad-shfl), store, loss ----
    #pragma unroll
    for (int i = 0; i < 4; ++i) {      // row R = row0 + w*32 + i*8 + g
        const int m = i >> 1, hi = i & 1;
        float inv = 1.0f / fmaxf(sqrtf(ssq[i]), 1e-12f);
        float s[16];
        #pragma unroll
        for (int j = 0; j < 8; ++j) {
            s[2 * j]     = acc[m][j][hi * 2]     * inv;
            s[2 * j + 1] = acc[m][j][hi * 2 + 1] * inv;
        }
        float mx = -1e30f;
        #pragma unroll
        for (int j = 0; j < 16; ++j) mx = fmaxf(mx, s[j] * alphav);
        mx = fmaxf(mx, __shfl_xor_sync(0xffffffffu, mx, 1));
        mx = fmaxf(mx, __shfl_xor_sync(0xffffffffu, mx, 2));
        float e[16];
        float es = 0.f, ps = 0.f;
        #pragma unroll
        for (int j = 0; j < 16; ++j) {
            e[j] = __expf(s[j] * alphav - mx);
            es += e[j];
            ps += e[j] * s[j];
        }
        es += __shfl_xor_sync(0xffffffffu, es, 1);
        es += __shfl_xor_sync(0xffffffffu, es, 2);
        ps += __shfl_xor_sync(0xffffffffu, ps, 1);
        ps += __shfl_xor_sync(0xffffffffu, ps, 2);
        float rs = 1.0f / es;
        if (tg == 0) lossacc += ps * rs;
        if (store_probs) {
            size_t R = row0 + (size_t)w * 32 + i * 8 + g;
            float* ob = out + (size_t)loss_off + R * KDIM + tg * 2;
            #pragma unroll
            for (int j = 0; j < 8; ++j) {   // scalar: out may be 4B-misaligned by loss_off
                ob[j * 8]     = e[2 * j] * rs;
                ob[j * 8 + 1] = e[2 * j + 1] * rs;
            }
        }
    }

    // ---- deterministic per-block loss partial ----
    #pragma unroll
    for (int o = 16; o; o >>= 1) lossacc += __shfl_xor_sync(0xffffffffu, lossacc, o);
    float* wred = (float*)(smem + SM_WRED);
    if (lane == 0) wred[w] = lossacc;
    __syncthreads();
    if (t == 0) {
        float ssum = 0.f;
        #pragma unroll
        for (int i = 0; i < 8; ++i) ssum += wred[i];
        g_partial[blockIdx.x] = ssum;
    }
}

// ---------------------------------------------------------------------------
// Kernel 3: deterministic loss finalize
// ---------------------------------------------------------------------------
__global__ void finalize_kernel(float* __restrict__ out, int nblocks, int N,
                                int write_loss) {
    if (!write_loss) return;
    __shared__ float sm[256];
    float s = 0.f;
    for (int i = threadIdx.x; i < nblocks; i += 256) s += g_partial[i];
    sm[threadIdx.x] = s;
    __syncthreads();
    for (int o = 128; o; o >>= 1) {
        if (threadIdx.x < o) sm[threadIdx.x] += sm[threadIdx.x + o];
        __syncthreads();
    }
    if (threadIdx.x == 0) out[0] = -sm[0] / (float)N;
}

// ---------------------------------------------------------------------------
extern "C" void kernel_launch(void* const* d_in, const int* in_sizes, int n_in,
                              void* d_out, int out_size) {
    const float* x        = (const float*)d_in[0];
    const float* clusters = (const float*)d_in[1];
    const float* alpha    = (const float*)d_in[2];
    float* out = (float*)d_out;

    int N = in_sizes[0] / DDIM;              // 131072
    int nblocks = N / TILE_ROWS;             // 512

    // Output layout (confirmed R5): out[0]=loss, out[1:]=probs when size nk+1
    long long nk = (long long)N * KDIM;
    int loss_off = 0, store_probs = 1, write_loss = 0;
    if ((long long)out_size == nk + 1) { loss_off = 1; write_loss = 1; }
    else if ((long long)out_size == nk) { loss_off = 0; write_loss = 0; }
    else { store_probs = 0; write_loss = 1; }

    cudaFuncSetAttribute(cluster_mma_kernel,
                         cudaFuncAttributeMaxDynamicSharedMemorySize, SMEM_TOTAL);

    norm_clusters_kernel<<<KDIM, 128>>>(clusters);
    cluster_mma_kernel<<<nblocks, THREADS, SMEM_TOTAL>>>(x, alpha, out,
                                                         loss_off, store_probs);
    finalize_kernel<<<1, 256>>>(out, nblocks, N, write_loss);
}

// round 11
// speedup vs baseline: 1.8424x; 1.2301x over previous
#include <cuda_runtime.h>
#include <math.h>
#include <stdint.h>

// Fixed shapes: x[131072,512] f32, clusters[64,512] f32, alpha scalar
#define DDIM 512
#define KDIM 64
#define TILE_ROWS 128
#define KC 16                    // k elements per cp.async chunk
#define NCH (DDIM / KC)          // 32 chunks
#define THREADS 256
#define APITCH 80                // bytes per A row in smem (16 floats + 4 pad)
#define ASTAGE (TILE_ROWS * APITCH)  // 10240 B

// SMEM layout (bytes): 4 A stages + wred
#define SM_A    0
#define SM_WRED (4 * ASTAGE)               // 40960
#define SMEM_TOTAL (SM_WRED + 32)          // 40992

#define MAXBLK 8192
__device__ float2 g_bf[64 * 256];          // B fragments [kk][j*32+lane], tf32-rounded
__device__ float g_partial[MAXBLK];        // per-block loss partials

// ---- helpers ---------------------------------------------------------------
static __device__ __forceinline__ uint32_t smem_u32(const void* p) {
    uint32_t a;
    asm("{ .reg .u64 t; cvta.to.shared.u64 t, %1; cvt.u32.u64 %0, t; }"
        : "=r"(a) : "l"(p));
    return a;
}
static __device__ __forceinline__ void cp16(uint32_t saddr, const void* g) {
    asm volatile("cp.async.cg.shared.global [%0], [%1], 16;" :: "r"(saddr), "l"(g));
}
#define CP_COMMIT() asm volatile("cp.async.commit_group;" ::: "memory")
#define CP_WAIT2()  asm volatile("cp.async.wait_group 2;" ::: "memory")

// Round-to-nearest tf32 (f32 bit pattern, low mantissa zeroed) — bias-free.
static __device__ __forceinline__ uint32_t rna_tf32(float v) {
    uint32_t r;
    asm("cvt.rna.tf32.f32 %0, %1;" : "=r"(r) : "f"(v));
    return r;
}

static __device__ __forceinline__ void mma_tf32(float* c,
                                                uint32_t a0, uint32_t a1,
                                                uint32_t a2, uint32_t a3,
                                                uint32_t b0, uint32_t b1) {
    asm volatile(
        "mma.sync.aligned.m16n8k8.row.col.f32.tf32.tf32.f32 "
        "{%0,%1,%2,%3}, {%4,%5,%6,%7}, {%8,%9}, {%0,%1,%2,%3};"
        : "+f"(c[0]), "+f"(c[1]), "+f"(c[2]), "+f"(c[3])
        : "r"(a0), "r"(a1), "r"(a2), "r"(a3), "r"(b0), "r"(b1));
}

// ---------------------------------------------------------------------------
// Kernel 1: L2-normalize clusters (RNA->tf32) and emit global B fragments.
// Block k handles cluster k.  B-frag layout (m16n8k8 col-major B):
//   g_bf[kk*256 + j*32 + lane] = { cn[n][kk*8+tg], cn[n][kk*8+tg+4] }
//   with n = j*8 + (lane>>2), tg = lane&3.  For cluster n=k:
//   j = k>>3, lane = (k&7)*4 + tt.
// ---------------------------------------------------------------------------
__global__ void norm_clusters_kernel(const float* __restrict__ clusters) {
    int k = blockIdx.x;          // 64 blocks
    int t = threadIdx.x;         // 128 threads
    float4 v = ((const float4*)(clusters + (size_t)k * DDIM))[t];
    float ss = v.x * v.x + v.y * v.y + v.z * v.z + v.w * v.w;
    #pragma unroll
    for (int o = 16; o; o >>= 1) ss += __shfl_xor_sync(0xffffffffu, ss, o);
    __shared__ float ws[4];
    __shared__ float s_inv;
    __shared__ float sc[DDIM];
    if ((t & 31) == 0) ws[t >> 5] = ss;
    __syncthreads();
    if (t == 0) {
        float s = ws[0] + ws[1] + ws[2] + ws[3];
        s_inv = 1.0f / fmaxf(sqrtf(s), 1e-12f);
    }
    __syncthreads();
    float iv = s_inv;
    sc[t * 4 + 0] = __uint_as_float(rna_tf32(v.x * iv));
    sc[t * 4 + 1] = __uint_as_float(rna_tf32(v.y * iv));
    sc[t * 4 + 2] = __uint_as_float(rna_tf32(v.z * iv));
    sc[t * 4 + 3] = __uint_as_float(rna_tf32(v.w * iv));
    __syncthreads();
    // 256 fragment entries for this cluster, 2 per thread
    #pragma unroll
    for (int e = t; e < 256; e += 128) {
        int kk = e >> 2, tt = e & 3;
        int lane = ((k & 7) << 2) | tt;
        g_bf[kk * 256 + ((k >> 3) << 5) + lane] =
            make_float2(sc[kk * 8 + tt], sc[kk * 8 + tt + 4]);
    }
}

// ---------------------------------------------------------------------------
// Kernel 2: tf32(RNA) mma.sync GEMM tile 128x64 + fused normalize/softmax/loss
// Warp w owns rows w*16..w*16+15 (one m16 tile) x all 64 cols (8 n8 tiles).
// 3 CTAs/SM (41 KB smem, <=85 regs).
// ---------------------------------------------------------------------------
__global__ __launch_bounds__(THREADS, 3)
void cluster_mma_kernel(const float* __restrict__ x,
                        const float* __restrict__ alphap,
                        float* __restrict__ out,
                        int loss_off, int store_probs) {
    extern __shared__ char smem[];
    const uint32_t sb = smem_u32(smem);
    const int t = threadIdx.x;
    const int w = t >> 5, lane = t & 31;
    const int g = lane >> 2, tg = lane & 3;
    const size_t row0 = (size_t)blockIdx.x * TILE_ROWS;

    // A-load mapping: 2 threads per row, 32 B each
    const int lr = t >> 1, lh = t & 1;
    const float* xsrc = x + (row0 + lr) * DDIM + lh * 8;
    const uint32_t asd = sb + SM_A + lr * APITCH + lh * 32;

    // ---- prologue: prefetch chunks 0..2 ----
    #pragma unroll
    for (int pc = 0; pc < 3; ++pc) {
        uint32_t ab = asd + pc * ASTAGE;
        const float* src = xsrc + pc * KC;
        cp16(ab, src);
        cp16(ab + 16, src + 4);
        CP_COMMIT();
    }

    float acc[8][4];
    #pragma unroll
    for (int j = 0; j < 8; ++j)
        #pragma unroll
        for (int r = 0; r < 4; ++r) acc[j][r] = 0.f;
    float ssq[2] = {0.f, 0.f};

    // ---- mainloop ----
    for (int c = 0; c < NCH; ++c) {
        CP_WAIT2();                 // chunk c landed
        __syncthreads();            // all warps past chunk c-1; its stage is free
        const int st = c & 3;

        if (c + 3 < NCH) {          // prefetch chunk c+3
            uint32_t ab = asd + ((c + 3) & 3) * ASTAGE;
            const float* src = xsrc + (c + 3) * KC;
            cp16(ab, src);
            cp16(ab + 16, src + 4);
        }
        CP_COMMIT();

        const char* ap = smem + SM_A + st * ASTAGE;

        // row sum-of-squares from this chunk (exact fp32, pre-rounding)
        #pragma unroll
        for (int i = 0; i < 2; ++i) {
            float4 v = *(const float4*)(ap + (w * 16 + i * 8 + g) * APITCH + tg * 16);
            ssq[i] += v.x * v.x + v.y * v.y + v.z * v.z + v.w * v.w;
        }

        // 2 k-steps of 8
        #pragma unroll
        for (int u = 0; u < 2; ++u) {
            const int kk = c * 2 + u;
            const float2* bp = g_bf + kk * 256 + lane;
            uint2 b[8];
            #pragma unroll
            for (int j = 0; j < 8; ++j)
                b[j] = __ldg((const uint2*)(bp + j * 32));

            const char* am = ap + (w * 16 + g) * APITCH + u * 32 + tg * 4;
            uint32_t a0 = rna_tf32(*(const float*)(am));
            uint32_t a1 = rna_tf32(*(const float*)(am + 8 * APITCH));
            uint32_t a2 = rna_tf32(*(const float*)(am + 16));
            uint32_t a3 = rna_tf32(*(const float*)(am + 8 * APITCH + 16));
            #pragma unroll
            for (int j = 0; j < 8; ++j)
                mma_tf32(acc[j], a0, a1, a2, a3, b[j].x, b[j].y);
        }
    }

    // ---- finalize norms: reduce over the 4 quad lanes ----
    #pragma unroll
    for (int i = 0; i < 2; ++i) {
        ssq[i] += __shfl_xor_sync(0xffffffffu, ssq[i], 1);
        ssq[i] += __shfl_xor_sync(0xffffffffu, ssq[i], 2);
    }

    const float alphav = *alphap;
    float lossacc = 0.f;

    // ---- epilogue: per-row scale, softmax over 64 (quad-shfl), store, loss ----
    #pragma unroll
    for (int i = 0; i < 2; ++i) {      // row R = row0 + w*16 + i*8 + g
        float inv = 1.0f / fmaxf(sqrtf(ssq[i]), 1e-12f);
        float s[16];
        #pragma unroll
        for (int j = 0; j < 8; ++j) {
            s[2 * j]     = acc[j][i * 2]     * inv;
            s[2 * j + 1] = acc[j][i * 2 + 1] * inv;
        }
        float mx = -1e30f;
        #pragma unroll
        for (int j = 0; j < 16; ++j) mx = fmaxf(mx, s[j] * alphav);
        mx = fmaxf(mx, __shfl_xor_sync(0xffffffffu, mx, 1));
        mx = fmaxf(mx, __shfl_xor_sync(0xffffffffu, mx, 2));
        float e[16];
        float es = 0.f, ps = 0.f;
        #pragma unroll
        for (int j = 0; j < 16; ++j) {
            e[j] = __expf(s[j] * alphav - mx);
            es += e[j];
            ps += e[j] * s[j];
        }
        es += __shfl_xor_sync(0xffffffffu, es, 1);
        es += __shfl_xor_sync(0xffffffffu, es, 2);
        ps += __shfl_xor_sync(0xffffffffu, ps, 1);
        ps += __shfl_xor_sync(0xffffffffu, ps, 2);
        float rs = 1.0f / es;
        if (tg == 0) lossacc += ps * rs;
        if (store_probs) {
            size_t R = row0 + (size_t)w * 16 + i * 8 + g;
            float* ob = out + (size_t)loss_off + R * KDIM + tg * 2;
            #pragma unroll
            for (int j = 0; j < 8; ++j) {   // scalar: out may be 4B-misaligned by loss_off
                ob[j * 8]     = e[2 * j] * rs;
                ob[j * 8 + 1] = e[2 * j + 1] * rs;
            }
        }
    }

    // ---- deterministic per-block loss partial ----
    #pragma unroll
    for (int o = 16; o; o >>= 1) lossacc += __shfl_xor_sync(0xffffffffu, lossacc, o);
    float* wred = (float*)(smem + SM_WRED);
    if (lane == 0) wred[w] = lossacc;
    __syncthreads();
    if (t == 0) {
        float ssum = 0.f;
        #pragma unroll
        for (int i = 0; i < 8; ++i) ssum += wred[i];
        g_partial[blockIdx.x] = ssum;
    }
}

// ---------------------------------------------------------------------------
// Kernel 3: deterministic loss finalize
// ---------------------------------------------------------------------------
__global__ void finalize_kernel(float* __restrict__ out, int nblocks, int N,
                                int write_loss) {
    if (!write_loss) return;
    __shared__ float sm[256];
    float s = 0.f;
    for (int i = threadIdx.x; i < nblocks; i += 256) s += g_partial[i];
    sm[threadIdx.x] = s;
    __syncthreads();
    for (int o = 128; o; o >>= 1) {
        if (threadIdx.x < o) sm[threadIdx.x] += sm[threadIdx.x + o];
        __syncthreads();
    }
    if (threadIdx.x == 0) out[0] = -sm[0] / (float)N;
}

// ---------------------------------------------------------------------------
extern "C" void kernel_launch(void* const* d_in, const int* in_sizes, int n_in,
                              void* d_out, int out_size) {
    const float* x        = (const float*)d_in[0];
    const float* clusters = (const float*)d_in[1];
    const float* alpha    = (const float*)d_in[2];
    float* out = (float*)d_out;

    int N = in_sizes[0] / DDIM;              // 131072
    int nblocks = N / TILE_ROWS;             // 1024

    // Output layout (confirmed): out[0]=loss, out[1:]=probs when size nk+1
    long long nk = (long long)N * KDIM;
    int loss_off = 0, store_probs = 1, write_loss = 0;
    if ((long long)out_size == nk + 1) { loss_off = 1; write_loss = 1; }
    else if ((long long)out_size == nk) { loss_off = 0; write_loss = 0; }
    else { store_probs = 0; write_loss = 1; }

    cudaFuncSetAttribute(cluster_mma_kernel,
                         cudaFuncAttributeMaxDynamicSharedMemorySize, SMEM_TOTAL);

    norm_clusters_kernel<<<KDIM, 128>>>(clusters);
    cluster_mma_kernel<<<nblocks, THREADS, SMEM_TOTAL>>>(x, alpha, out,
                                                         loss_off, store_probs);
    finalize_kernel<<<1, 256>>>(out, nblocks, N, write_loss);
}

// round 12
// speedup vs baseline: 2.0159x; 1.0942x over previous
#include <cuda_runtime.h>
#include <math.h>
#include <stdint.h>

// Fixed shapes: x[131072,512] f32, clusters[64,512] f32, alpha scalar
#define DDIM 512
#define KDIM 64
#define TILE_ROWS 128
#define KC 16                    // k elements per cp.async chunk
#define NCH (DDIM / KC)          // 32 chunks
#define THREADS 256
#define APITCH 80                // bytes per A row in smem (16 floats + 4 pad)
#define ASTAGE (TILE_ROWS * APITCH)  // 10240 B

// SMEM layout (bytes): 4 A stages + wred
#define SM_A    0
#define SM_WRED (4 * ASTAGE)               // 40960
#define SMEM_TOTAL (SM_WRED + 32)          // 40992

#define MAXBLK 8192
__device__ float2 g_bf[64 * 256];          // B fragments [kk][j*32+lane], tf32-rounded
__device__ float g_partial[MAXBLK];        // per-block loss partials

// ---- helpers ---------------------------------------------------------------
static __device__ __forceinline__ uint32_t smem_u32(const void* p) {
    uint32_t a;
    asm("{ .reg .u64 t; cvta.to.shared.u64 t, %1; cvt.u32.u64 %0, t; }"
        : "=r"(a) : "l"(p));
    return a;
}
static __device__ __forceinline__ void cp16(uint32_t saddr, const void* g) {
    asm volatile("cp.async.cg.shared.global [%0], [%1], 16;" :: "r"(saddr), "l"(g));
}
#define CP_COMMIT() asm volatile("cp.async.commit_group;" ::: "memory")
#define CP_WAIT2()  asm volatile("cp.async.wait_group 2;" ::: "memory")

// Round-to-nearest tf32 (f32 bit pattern, low mantissa zeroed) — bias-free.
static __device__ __forceinline__ uint32_t rna_tf32(float v) {
    uint32_t r;
    asm("cvt.rna.tf32.f32 %0, %1;" : "=r"(r) : "f"(v));
    return r;
}

static __device__ __forceinline__ void mma_tf32(float* c,
                                                uint32_t a0, uint32_t a1,
                                                uint32_t a2, uint32_t a3,
                                                uint32_t b0, uint32_t b1) {
    asm volatile(
        "mma.sync.aligned.m16n8k8.row.col.f32.tf32.tf32.f32 "
        "{%0,%1,%2,%3}, {%4,%5,%6,%7}, {%8,%9}, {%0,%1,%2,%3};"
        : "+f"(c[0]), "+f"(c[1]), "+f"(c[2]), "+f"(c[3])
        : "r"(a0), "r"(a1), "r"(a2), "r"(a3), "r"(b0), "r"(b1));
}

// ---------------------------------------------------------------------------
// Kernel 1: L2-normalize clusters (RNA->tf32) and emit global B fragments.
//   g_bf[kk*256 + j*32 + lane] = { cn[n][kk*8+tg], cn[n][kk*8+tg+4] }
//   with n = j*8 + (lane>>2), tg = lane&3.
// ---------------------------------------------------------------------------
__global__ void norm_clusters_kernel(const float* __restrict__ clusters) {
    int k = blockIdx.x;          // 64 blocks
    int t = threadIdx.x;         // 128 threads
    float4 v = ((const float4*)(clusters + (size_t)k * DDIM))[t];
    float ss = v.x * v.x + v.y * v.y + v.z * v.z + v.w * v.w;
    #pragma unroll
    for (int o = 16; o; o >>= 1) ss += __shfl_xor_sync(0xffffffffu, ss, o);
    __shared__ float ws[4];
    __shared__ float s_inv;
    __shared__ float sc[DDIM];
    if ((t & 31) == 0) ws[t >> 5] = ss;
    __syncthreads();
    if (t == 0) {
        float s = ws[0] + ws[1] + ws[2] + ws[3];
        s_inv = 1.0f / fmaxf(sqrtf(s), 1e-12f);
    }
    __syncthreads();
    float iv = s_inv;
    sc[t * 4 + 0] = __uint_as_float(rna_tf32(v.x * iv));
    sc[t * 4 + 1] = __uint_as_float(rna_tf32(v.y * iv));
    sc[t * 4 + 2] = __uint_as_float(rna_tf32(v.z * iv));
    sc[t * 4 + 3] = __uint_as_float(rna_tf32(v.w * iv));
    __syncthreads();
    #pragma unroll
    for (int e = t; e < 256; e += 128) {
        int kk = e >> 2, tt = e & 3;
        int lane = ((k & 7) << 2) | tt;
        g_bf[kk * 256 + ((k >> 3) << 5) + lane] =
            make_float2(sc[kk * 8 + tt], sc[kk * 8 + tt + 4]);
    }
}

// ---------------------------------------------------------------------------
// Kernel 2: tf32(RNA) mma.sync GEMM tile 128x64 + fused normalize/softmax/loss
// Warp w owns rows w*16..w*16+15 and LOADS THEM ITSELF (warp-private cp.async
// pipeline, no block barrier in the mainloop). 3 CTAs/SM.
// ---------------------------------------------------------------------------
__global__ __launch_bounds__(THREADS, 3)
void cluster_mma_kernel(const float* __restrict__ x,
                        const float* __restrict__ alphap,
                        float* __restrict__ out,
                        int loss_off, int store_probs) {
    extern __shared__ char smem[];
    const uint32_t sb = smem_u32(smem);
    const int t = threadIdx.x;
    const int w = t >> 5, lane = t & 31;
    const int g = lane >> 2, tg = lane & 3;
    const size_t row0 = (size_t)blockIdx.x * TILE_ROWS;

    // warp-private A load mapping: lane l -> row w*16 + (l>>1), half (l&1)
    const int lr = w * 16 + (lane >> 1), lh = lane & 1;
    const float* xsrc = x + (row0 + lr) * DDIM + lh * 8;
    const uint32_t asd = sb + SM_A + lr * APITCH + lh * 32;

    // ---- prologue: prefetch chunks 0..2 (this warp's rows only) ----
    #pragma unroll
    for (int pc = 0; pc < 3; ++pc) {
        uint32_t ab = asd + pc * ASTAGE;
        const float* src = xsrc + pc * KC;
        cp16(ab, src);
        cp16(ab + 16, src + 4);
        CP_COMMIT();
    }

    float acc[8][4];
    #pragma unroll
    for (int j = 0; j < 8; ++j)
        #pragma unroll
        for (int r = 0; r < 4; ++r) acc[j][r] = 0.f;
    float ssq[2] = {0.f, 0.f};

    // ---- mainloop: no __syncthreads; per-warp pipeline ----
    for (int c = 0; c < NCH; ++c) {
        CP_WAIT2();                 // this warp's chunk c landed
        __syncwarp();               // cross-lane visibility within the warp
        const int st = c & 3;

        if (c + 3 < NCH) {          // prefetch chunk c+3 (stage was consumed at c-1)
            uint32_t ab = asd + ((c + 3) & 3) * ASTAGE;
            const float* src = xsrc + (c + 3) * KC;
            cp16(ab, src);
            cp16(ab + 16, src + 4);
        }
        CP_COMMIT();

        const char* ap = smem + SM_A + st * ASTAGE;

        // row sum-of-squares from this chunk (exact fp32, pre-rounding)
        #pragma unroll
        for (int i = 0; i < 2; ++i) {
            float4 v = *(const float4*)(ap + (w * 16 + i * 8 + g) * APITCH + tg * 16);
            ssq[i] += v.x * v.x + v.y * v.y + v.z * v.z + v.w * v.w;
        }

        // 2 k-steps of 8
        #pragma unroll
        for (int u = 0; u < 2; ++u) {
            const int kk = c * 2 + u;
            const float2* bp = g_bf + kk * 256 + lane;
            uint2 b[8];
            #pragma unroll
            for (int j = 0; j < 8; ++j)
                b[j] = __ldg((const uint2*)(bp + j * 32));

            const char* am = ap + (w * 16 + g) * APITCH + u * 32 + tg * 4;
            uint32_t a0 = rna_tf32(*(const float*)(am));
            uint32_t a1 = rna_tf32(*(const float*)(am + 8 * APITCH));
            uint32_t a2 = rna_tf32(*(const float*)(am + 16));
            uint32_t a3 = rna_tf32(*(const float*)(am + 8 * APITCH + 16));
            #pragma unroll
            for (int j = 0; j < 8; ++j)
                mma_tf32(acc[j], a0, a1, a2, a3, b[j].x, b[j].y);
        }
    }

    // ---- finalize norms: reduce over the 4 quad lanes ----
    #pragma unroll
    for (int i = 0; i < 2; ++i) {
        ssq[i] += __shfl_xor_sync(0xffffffffu, ssq[i], 1);
        ssq[i] += __shfl_xor_sync(0xffffffffu, ssq[i], 2);
    }

    const float alphav = *alphap;
    float lossacc = 0.f;

    // ---- epilogue: per-row scale, softmax over 64 (quad-shfl), store, loss ----
    #pragma unroll
    for (int i = 0; i < 2; ++i) {      // row R = row0 + w*16 + i*8 + g
        float inv = 1.0f / fmaxf(sqrtf(ssq[i]), 1e-12f);
        float s[16];
        #pragma unroll
        for (int j = 0; j < 8; ++j) {
            s[2 * j]     = acc[j][i * 2]     * inv;
            s[2 * j + 1] = acc[j][i * 2 + 1] * inv;
        }
        float mx = -1e30f;
        #pragma unroll
        for (int j = 0; j < 16; ++j) mx = fmaxf(mx, s[j] * alphav);
        mx = fmaxf(mx, __shfl_xor_sync(0xffffffffu, mx, 1));
        mx = fmaxf(mx, __shfl_xor_sync(0xffffffffu, mx, 2));
        float e[16];
        float es = 0.f, ps = 0.f;
        #pragma unroll
        for (int j = 0; j < 16; ++j) {
            e[j] = __expf(s[j] * alphav - mx);
            es += e[j];
            ps += e[j] * s[j];
        }
        es += __shfl_xor_sync(0xffffffffu, es, 1);
        es += __shfl_xor_sync(0xffffffffu, es, 2);
        ps += __shfl_xor_sync(0xffffffffu, ps, 1);
        ps += __shfl_xor_sync(0xffffffffu, ps, 2);
        float rs = 1.0f / es;
        if (tg == 0) lossacc += ps * rs;
        if (store_probs) {
            size_t R = row0 + (size_t)w * 16 + i * 8 + g;
            float* ob = out + (size_t)loss_off + R * KDIM + tg * 2;
            #pragma unroll
            for (int j = 0; j < 8; ++j) {   // scalar: out may be 4B-misaligned by loss_off
                ob[j * 8]     = e[2 * j] * rs;
                ob[j * 8 + 1] = e[2 * j + 1] * rs;
            }
        }
    }

    // ---- deterministic per-block loss partial ----
    #pragma unroll
    for (int o = 16; o; o >>= 1) lossacc += __shfl_xor_sync(0xffffffffu, lossacc, o);
    float* wred = (float*)(smem + SM_WRED);
    if (lane == 0) wred[w] = lossacc;
    __syncthreads();
    if (t == 0) {
        float ssum = 0.f;
        #pragma unroll
        for (int i = 0; i < 8; ++i) ssum += wred[i];
        g_partial[blockIdx.x] = ssum;
    }
}

// ---------------------------------------------------------------------------
// Kernel 3: deterministic loss finalize
// ---------------------------------------------------------------------------
__global__ void finalize_kernel(float* __restrict__ out, int nblocks, int N,
                                int write_loss) {
    if (!write_loss) return;
    __shared__ float sm[256];
    float s = 0.f;
    for (int i = threadIdx.x; i < nblocks; i += 256) s += g_partial[i];
    sm[threadIdx.x] = s;
    __syncthreads();
    for (int o = 128; o; o >>= 1) {
        if (threadIdx.x < o) sm[threadIdx.x] += sm[threadIdx.x + o];
        __syncthreads();
    }
    if (threadIdx.x == 0) out[0] = -sm[0] / (float)N;
}

// ---------------------------------------------------------------------------
extern "C" void kernel_launch(void* const* d_in, const int* in_sizes, int n_in,
                              void* d_out, int out_size) {
    const float* x        = (const float*)d_in[0];
    const float* clusters = (const float*)d_in[1];
    const float* alpha    = (const float*)d_in[2];
    float* out = (float*)d_out;

    int N = in_sizes[0] / DDIM;              // 131072
    int nblocks = N / TILE_ROWS;             // 1024

    // Output layout (confirmed): out[0]=loss, out[1:]=probs when size nk+1
    long long nk = (long long)N * KDIM;
    int loss_off = 0, store_probs = 1, write_loss = 0;
    if ((long long)out_size == nk + 1) { loss_off = 1; write_loss = 1; }
    else if ((long long)out_size == nk) { loss_off = 0; write_loss = 0; }
    else { store_probs = 0; write_loss = 1; }

    cudaFuncSetAttribute(cluster_mma_kernel,
                         cudaFuncAttributeMaxDynamicSharedMemorySize, SMEM_TOTAL);

    norm_clusters_kernel<<<KDIM, 128>>>(clusters);
    cluster_mma_kernel<<<nblocks, THREADS, SMEM_TOTAL>>>(x, alpha, out,
                                                         loss_off, store_probs);
    finalize_kernel<<<1, 256>>>(out, nblocks, N, write_loss);
}

// round 13
// speedup vs baseline: 2.5927x; 1.2862x over previous
#include <cuda_runtime.h>
#include <math.h>
#include <stdint.h>

// Fixed shapes: x[131072,512] f32, clusters[64,512] f32, alpha scalar
#define DDIM 512
#define KDIM 64
#define TILE_ROWS 128
#define KC 16                    // k elements per cp.async chunk
#define NCH (DDIM / KC)          // 32 chunks
#define THREADS 128              // 4 warps; warp w owns rows w*32..w*32+31
#define APITCH 80                // bytes per A row in smem (16 floats + 4 pad)
#define ASTAGE (TILE_ROWS * APITCH)  // 10240 B

// SMEM layout (bytes): 4 A stages + wred
#define SM_A    0
#define SM_WRED (4 * ASTAGE)               // 40960
#define SMEM_TOTAL (SM_WRED + 16)          // 40976

#define MAXBLK 8192
__device__ float2 g_bf[64 * 256];          // B fragments [kk][j*32+lane], tf32-rounded
__device__ float g_partial[MAXBLK];        // per-block loss partials

// ---- helpers ---------------------------------------------------------------
static __device__ __forceinline__ uint32_t smem_u32(const void* p) {
    uint32_t a;
    asm("{ .reg .u64 t; cvta.to.shared.u64 t, %1; cvt.u32.u64 %0, t; }"
        : "=r"(a) : "l"(p));
    return a;
}
static __device__ __forceinline__ void cp16(uint32_t saddr, const void* g) {
    asm volatile("cp.async.cg.shared.global [%0], [%1], 16;" :: "r"(saddr), "l"(g));
}
#define CP_COMMIT() asm volatile("cp.async.commit_group;" ::: "memory")
#define CP_WAIT2()  asm volatile("cp.async.wait_group 2;" ::: "memory")

// Round-to-nearest tf32 (f32 bit pattern, low mantissa zeroed) — bias-free.
static __device__ __forceinline__ uint32_t rna_tf32(float v) {
    uint32_t r;
    asm("cvt.rna.tf32.f32 %0, %1;" : "=r"(r) : "f"(v));
    return r;
}

static __device__ __forceinline__ void mma_tf32(float* c,
                                                uint32_t a0, uint32_t a1,
                                                uint32_t a2, uint32_t a3,
                                                uint32_t b0, uint32_t b1) {
    asm volatile(
        "mma.sync.aligned.m16n8k8.row.col.f32.tf32.tf32.f32 "
        "{%0,%1,%2,%3}, {%4,%5,%6,%7}, {%8,%9}, {%0,%1,%2,%3};"
        : "+f"(c[0]), "+f"(c[1]), "+f"(c[2]), "+f"(c[3])
        : "r"(a0), "r"(a1), "r"(a2), "r"(a3), "r"(b0), "r"(b1));
}

// ---------------------------------------------------------------------------
// Kernel 1: L2-normalize clusters (RNA->tf32) and emit global B fragments.
//   g_bf[kk*256 + j*32 + lane] = { cn[n][kk*8+tg], cn[n][kk*8+tg+4] }
//   with n = j*8 + (lane>>2), tg = lane&3.
// ---------------------------------------------------------------------------
__global__ void norm_clusters_kernel(const float* __restrict__ clusters) {
    int k = blockIdx.x;          // 64 blocks
    int t = threadIdx.x;         // 128 threads
    float4 v = ((const float4*)(clusters + (size_t)k * DDIM))[t];
    float ss = v.x * v.x + v.y * v.y + v.z * v.z + v.w * v.w;
    #pragma unroll
    for (int o = 16; o; o >>= 1) ss += __shfl_xor_sync(0xffffffffu, ss, o);
    __shared__ float ws[4];
    __shared__ float s_inv;
    __shared__ float sc[DDIM];
    if ((t & 31) == 0) ws[t >> 5] = ss;
    __syncthreads();
    if (t == 0) {
        float s = ws[0] + ws[1] + ws[2] + ws[3];
        s_inv = 1.0f / fmaxf(sqrtf(s), 1e-12f);
    }
    __syncthreads();
    float iv = s_inv;
    sc[t * 4 + 0] = __uint_as_float(rna_tf32(v.x * iv));
    sc[t * 4 + 1] = __uint_as_float(rna_tf32(v.y * iv));
    sc[t * 4 + 2] = __uint_as_float(rna_tf32(v.z * iv));
    sc[t * 4 + 3] = __uint_as_float(rna_tf32(v.w * iv));
    __syncthreads();
    #pragma unroll
    for (int e = t; e < 256; e += 128) {
        int kk = e >> 2, tt = e & 3;
        int lane = ((k & 7) << 2) | tt;
        g_bf[kk * 256 + ((k >> 3) << 5) + lane] =
            make_float2(sc[kk * 8 + tt], sc[kk * 8 + tt + 4]);
    }
}

// ---------------------------------------------------------------------------
// Kernel 2: tf32(RNA) mma.sync GEMM tile 128x64 + fused normalize/softmax/loss
// 128 threads. Warp w owns rows w*32..w*32+31 (2 x m16 tiles, shared B frags)
// and loads them itself (warp-private cp.async pipeline; no block barriers).
// 4 CTAs/SM.
// ---------------------------------------------------------------------------
__global__ __launch_bounds__(THREADS, 4)
void cluster_mma_kernel(const float* __restrict__ x,
                        const float* __restrict__ alphap,
                        float* __restrict__ out,
                        int loss_off, int store_probs) {
    extern __shared__ char smem[];
    const uint32_t sb = smem_u32(smem);
    const int t = threadIdx.x;
    const int w = t >> 5, lane = t & 31;
    const int g = lane >> 2, tg = lane & 3;
    const size_t row0 = (size_t)blockIdx.x * TILE_ROWS;

    // warp-private A load mapping: lane l -> full 64B chunk of row w*32 + l
    const int lr = w * 32 + lane;
    const float* xsrc = x + (row0 + lr) * DDIM;
    const uint32_t asd = sb + SM_A + lr * APITCH;

    // ---- prologue: prefetch chunks 0..2 (this warp's rows only) ----
    #pragma unroll
    for (int pc = 0; pc < 3; ++pc) {
        uint32_t ab = asd + pc * ASTAGE;
        const float* src = xsrc + pc * KC;
        cp16(ab, src);
        cp16(ab + 16, src + 4);
        cp16(ab + 32, src + 8);
        cp16(ab + 48, src + 12);
        CP_COMMIT();
    }

    float acc[2][8][4];
    #pragma unroll
    for (int m = 0; m < 2; ++m)
        #pragma unroll
        for (int j = 0; j < 8; ++j)
            #pragma unroll
            for (int r = 0; r < 4; ++r) acc[m][j][r] = 0.f;
    float ssq[4] = {0.f, 0.f, 0.f, 0.f};

    // ---- mainloop: warp-private pipeline, no __syncthreads ----
    for (int c = 0; c < NCH; ++c) {
        CP_WAIT2();                 // this warp's chunk c landed
        __syncwarp();
        const int st = c & 3;

        if (c + 3 < NCH) {          // prefetch chunk c+3
            uint32_t ab = asd + ((c + 3) & 3) * ASTAGE;
            const float* src = xsrc + (c + 3) * KC;
            cp16(ab, src);
            cp16(ab + 16, src + 4);
            cp16(ab + 32, src + 8);
            cp16(ab + 48, src + 12);
        }
        CP_COMMIT();

        const char* ap = smem + SM_A + st * ASTAGE;

        // 2 k-steps of 8; B frags shared across both m16 tiles
        #pragma unroll
        for (int u = 0; u < 2; ++u) {
            const int kk = c * 2 + u;
            const float2* bp = g_bf + kk * 256 + lane;
            uint2 b[8];
            #pragma unroll
            for (int j = 0; j < 8; ++j)
                b[j] = __ldg((const uint2*)(bp + j * 32));

            #pragma unroll
            for (int m = 0; m < 2; ++m) {
                const char* am = ap + (w * 32 + m * 16 + g) * APITCH + u * 32 + tg * 4;
                float f0 = *(const float*)(am);
                float f1 = *(const float*)(am + 8 * APITCH);
                float f2 = *(const float*)(am + 16);
                float f3 = *(const float*)(am + 8 * APITCH + 16);
                // row sum-of-squares from the same scalars (exact fp32)
                ssq[2 * m]     += f0 * f0 + f2 * f2;
                ssq[2 * m + 1] += f1 * f1 + f3 * f3;
                uint32_t a0 = rna_tf32(f0);
                uint32_t a1 = rna_tf32(f1);
                uint32_t a2 = rna_tf32(f2);
                uint32_t a3 = rna_tf32(f3);
                #pragma unroll
                for (int j = 0; j < 8; ++j)
                    mma_tf32(acc[m][j], a0, a1, a2, a3, b[j].x, b[j].y);
            }
        }
    }

    // ---- finalize norms: reduce over the 4 quad (tg) lanes ----
    #pragma unroll
    for (int i = 0; i < 4; ++i) {
        ssq[i] += __shfl_xor_sync(0xffffffffu, ssq[i], 1);
        ssq[i] += __shfl_xor_sync(0xffffffffu, ssq[i], 2);
    }

    const float alphav = *alphap;
    float lossacc = 0.f;

    // ---- epilogue: per-row scale, softmax over 64 (quad-shfl), store, loss ----
    #pragma unroll
    for (int i = 0; i < 4; ++i) {      // row R = row0 + w*32 + i*8 + g
        const int m = i >> 1, hi = i & 1;
        float inv = 1.0f / fmaxf(sqrtf(ssq[i]), 1e-12f);
        float s[16];
        #pragma unroll
        for (int j = 0; j < 8; ++j) {
            s[2 * j]     = acc[m][j][hi * 2]     * inv;
            s[2 * j + 1] = acc[m][j][hi * 2 + 1] * inv;
        }
        float mx = -1e30f;
        #pragma unroll
        for (int j = 0; j < 16; ++j) mx = fmaxf(mx, s[j] * alphav);
        mx = fmaxf(mx, __shfl_xor_sync(0xffffffffu, mx, 1));
        mx = fmaxf(mx, __shfl_xor_sync(0xffffffffu, mx, 2));
        float e[16];
        float es = 0.f, ps = 0.f;
        #pragma unroll
        for (int j = 0; j < 16; ++j) {
            e[j] = __expf(s[j] * alphav - mx);
            es += e[j];
            ps += e[j] * s[j];
        }
        es += __shfl_xor_sync(0xffffffffu, es, 1);
        es += __shfl_xor_sync(0xffffffffu, es, 2);
        ps += __shfl_xor_sync(0xffffffffu, ps, 1);
        ps += __shfl_xor_sync(0xffffffffu, ps, 2);
        float rs = 1.0f / es;
        if (tg == 0) lossacc += ps * rs;
        if (store_probs) {
            size_t R = row0 + (size_t)w * 32 + i * 8 + g;
            float* ob = out + (size_t)loss_off + R * KDIM + tg * 2;
            #pragma unroll
            for (int j = 0; j < 8; ++j) {   // scalar: out may be 4B-misaligned by loss_off
                ob[j * 8]     = e[2 * j] * rs;
                ob[j * 8 + 1] = e[2 * j + 1] * rs;
            }
        }
    }

    // ---- deterministic per-block loss partial ----
    #pragma unroll
    for (int o = 16; o; o >>= 1) lossacc += __shfl_xor_sync(0xffffffffu, lossacc, o);
    float* wred = (float*)(smem + SM_WRED);
    if (lane == 0) wred[w] = lossacc;
    __syncthreads();
    if (t == 0) {
        float ssum = wred[0] + wred[1] + wred[2] + wred[3];
        g_partial[blockIdx.x] = ssum;
    }
}

// ---------------------------------------------------------------------------
// Kernel 3: deterministic loss finalize
// ---------------------------------------------------------------------------
__global__ void finalize_kernel(float* __restrict__ out, int nblocks, int N,
                                int write_loss) {
    if (!write_loss) return;
    __shared__ float sm[256];
    float s = 0.f;
    for (int i = threadIdx.x; i < nblocks; i += 256) s += g_partial[i];
    sm[threadIdx.x] = s;
    __syncthreads();
    for (int o = 128; o; o >>= 1) {
        if (threadIdx.x < o) sm[threadIdx.x] += sm[threadIdx.x + o];
        __syncthreads();
    }
    if (threadIdx.x == 0) out[0] = -sm[0] / (float)N;
}

// ---------------------------------------------------------------------------
extern "C" void kernel_launch(void* const* d_in, const int* in_sizes, int n_in,
                              void* d_out, int out_size) {
    const float* x        = (const float*)d_in[0];
    const float* clusters = (const float*)d_in[1];
    const float* alpha    = (const float*)d_in[2];
    float* out = (float*)d_out;

    int N = in_sizes[0] / DDIM;              // 131072
    int nblocks = N / TILE_ROWS;             // 1024

    // Output layout (confirmed): out[0]=loss, out[1:]=probs when size nk+1
    long long nk = (long long)N * KDIM;
    int loss_off = 0, store_probs = 1, write_loss = 0;
    if ((long long)out_size == nk + 1) { loss_off = 1; write_loss = 1; }
    else if ((long long)out_size == nk) { loss_off = 0; write_loss = 0; }
    else { store_probs = 0; write_loss = 1; }

    cudaFuncSetAttribute(cluster_mma_kernel,
                         cudaFuncAttributeMaxDynamicSharedMemorySize, SMEM_TOTAL);

    norm_clusters_kernel<<<KDIM, 128>>>(clusters);
    cluster_mma_kernel<<<nblocks, THREADS, SMEM_TOTAL>>>(x, alpha, out,
                                                         loss_off, store_probs);
    finalize_kernel<<<1, 256>>>(out, nblocks, N, write_loss);
}

// round 14
// speedup vs baseline: 2.8759x; 1.1092x over previous
#include <cuda_runtime.h>
#include <math.h>
#include <stdint.h>

// Fixed shapes: x[131072,512] f32, clusters[64,512] f32, alpha scalar
#define DDIM 512
#define KDIM 64
#define TILE_ROWS 128
#define KC 16                    // k elements per chunk = one m16n8k16 k-step
#define NCH (DDIM / KC)          // 32 chunks
#define THREADS 128              // 4 warps; warp w owns rows w*32..w*32+31
#define APITCH 80                // bytes per A row in smem (16 floats + 4 pad)
#define ASTAGE (TILE_ROWS * APITCH)  // 10240 B
#define NSTAGE 3

// SMEM layout (bytes): 3 A stages + wred
#define SM_A    0
#define SM_WRED (NSTAGE * ASTAGE)          // 30720
#define SMEM_TOTAL (SM_WRED + 16)          // 30736

#define MAXBLK 8192
__device__ uint2 g_bfh[32 * 256];          // bf16 B fragments [ks16][j*32+lane] = {b0,b1}
__device__ float g_partial[MAXBLK];        // per-block loss partials

// ---- helpers ---------------------------------------------------------------
static __device__ __forceinline__ uint32_t smem_u32(const void* p) {
    uint32_t a;
    asm("{ .reg .u64 t; cvta.to.shared.u64 t, %1; cvt.u32.u64 %0, t; }"
        : "=r"(a) : "l"(p));
    return a;
}
static __device__ __forceinline__ void cp16(uint32_t saddr, const void* g) {
    asm volatile("cp.async.cg.shared.global [%0], [%1], 16;" :: "r"(saddr), "l"(g));
}
#define CP_COMMIT() asm volatile("cp.async.commit_group;" ::: "memory")
#define CP_WAIT1()  asm volatile("cp.async.wait_group 1;" ::: "memory")

// pack two f32 -> bf16x2 (round-to-nearest-even; low half = first arg)
static __device__ __forceinline__ uint32_t pack_bf16(float lo, float hi) {
    uint32_t r;
    asm("cvt.rn.bf16x2.f32 %0, %1, %2;" : "=r"(r) : "f"(hi), "f"(lo));
    return r;
}

static __device__ __forceinline__ void mma_bf16(float* c,
                                                uint32_t a0, uint32_t a1,
                                                uint32_t a2, uint32_t a3,
                                                uint32_t b0, uint32_t b1) {
    asm volatile(
        "mma.sync.aligned.m16n8k16.row.col.f32.bf16.bf16.f32 "
        "{%0,%1,%2,%3}, {%4,%5,%6,%7}, {%8,%9}, {%0,%1,%2,%3};"
        : "+f"(c[0]), "+f"(c[1]), "+f"(c[2]), "+f"(c[3])
        : "r"(a0), "r"(a1), "r"(a2), "r"(a3), "r"(b0), "r"(b1));
}

// ---------------------------------------------------------------------------
// Kernel 1: L2-normalize clusters, emit bf16 B fragments (m16n8k16 col-major).
//   For kstep ks, col n = j*8 + (lane>>2), lane quad tg = lane&3:
//     b0 = {cn[n][ks*16+2tg], cn[n][ks*16+2tg+1]}, b1 = same +8.
//   Cluster k occupies j = k>>3, lanes (k&7)*4 + tg.
// ---------------------------------------------------------------------------
__global__ void norm_clusters_kernel(const float* __restrict__ clusters) {
    int k = blockIdx.x;          // 64 blocks
    int t = threadIdx.x;         // 128 threads
    float4 v = ((const float4*)(clusters + (size_t)k * DDIM))[t];
    float ss = v.x * v.x + v.y * v.y + v.z * v.z + v.w * v.w;
    #pragma unroll
    for (int o = 16; o; o >>= 1) ss += __shfl_xor_sync(0xffffffffu, ss, o);
    __shared__ float ws[4];
    __shared__ float s_inv;
    __shared__ float sc[DDIM];
    if ((t & 31) == 0) ws[t >> 5] = ss;
    __syncthreads();
    if (t == 0) {
        float s = ws[0] + ws[1] + ws[2] + ws[3];
        s_inv = 1.0f / fmaxf(sqrtf(s), 1e-12f);
    }
    __syncthreads();
    float iv = s_inv;
    sc[t * 4 + 0] = v.x * iv;
    sc[t * 4 + 1] = v.y * iv;
    sc[t * 4 + 2] = v.z * iv;
    sc[t * 4 + 3] = v.w * iv;
    __syncthreads();
    // 128 entries: ks = t>>2 (0..31), tg = t&3
    {
        int ks = t >> 2, tg = t & 3;
        const float* s = sc + ks * 16 + tg * 2;
        uint2 b;
        b.x = pack_bf16(s[0], s[1]);
        b.y = pack_bf16(s[8], s[9]);
        g_bfh[ks * 256 + ((k >> 3) << 5) + ((k & 7) << 2) + tg] = b;
    }
}

// ---------------------------------------------------------------------------
// Kernel 2: bf16 m16n8k16 GEMM tile 128x64 + fused normalize/softmax/loss.
// 128 threads; warp w owns rows w*32..w*32+31 (2 m16 tiles) and loads them
// itself (warp-private 3-stage cp.async pipeline; no block barriers).
// ---------------------------------------------------------------------------
__global__ __launch_bounds__(THREADS, 4)
void cluster_mma_kernel(const float* __restrict__ x,
                        const float* __restrict__ alphap,
                        float* __restrict__ out,
                        int loss_off, int store_probs) {
    extern __shared__ char smem[];
    const uint32_t sb = smem_u32(smem);
    const int t = threadIdx.x;
    const int w = t >> 5, lane = t & 31;
    const int g = lane >> 2, tg = lane & 3;
    const size_t row0 = (size_t)blockIdx.x * TILE_ROWS;

    // warp-private A load mapping: lane l -> full 64B chunk of row w*32 + l
    const int lr = w * 32 + lane;
    const float* xsrc = x + (row0 + lr) * DDIM;
    const uint32_t asd = sb + SM_A + lr * APITCH;

    // ---- prologue: prefetch chunks 0,1 ----
    #pragma unroll
    for (int pc = 0; pc < 2; ++pc) {
        uint32_t ab = asd + pc * ASTAGE;
        const float* src = xsrc + pc * KC;
        cp16(ab, src);
        cp16(ab + 16, src + 4);
        cp16(ab + 32, src + 8);
        cp16(ab + 48, src + 12);
        CP_COMMIT();
    }

    float acc[2][8][4];
    #pragma unroll
    for (int m = 0; m < 2; ++m)
        #pragma unroll
        for (int j = 0; j < 8; ++j)
            #pragma unroll
            for (int r = 0; r < 4; ++r) acc[m][j][r] = 0.f;
    float ssq[4] = {0.f, 0.f, 0.f, 0.f};

    // ---- mainloop: warp-private pipeline, no __syncthreads ----
    for (int c = 0; c < NCH; ++c) {
        // B fragments for this k-step (L1-resident, independent of cp.async)
        const uint2* bp = g_bfh + c * 256 + lane;
        uint2 b[8];
        #pragma unroll
        for (int j = 0; j < 8; ++j)
            b[j] = __ldg(bp + j * 32);

        CP_WAIT1();                 // chunk c landed (c+1 may stay in flight)
        __syncwarp();
        const int st = c % NSTAGE;

        if (c + 2 < NCH) {          // prefetch chunk c+2 into freed stage
            uint32_t ab = asd + ((c + 2) % NSTAGE) * ASTAGE;
            const float* src = xsrc + (c + 2) * KC;
            cp16(ab, src);
            cp16(ab + 16, src + 4);
            cp16(ab + 32, src + 8);
            cp16(ab + 48, src + 12);
        }
        CP_COMMIT();

        const char* ap = smem + SM_A + st * ASTAGE;

        #pragma unroll
        for (int m = 0; m < 2; ++m) {
            const char* r0 = ap + (w * 32 + m * 16 + g) * APITCH + tg * 8;
            const char* r1 = r0 + 8 * APITCH;
            float2 v0 = *(const float2*)(r0);        // row g,   k=2tg,2tg+1
            float2 v1 = *(const float2*)(r1);        // row g+8, k=2tg,2tg+1
            float2 v2 = *(const float2*)(r0 + 32);   // row g,   k=2tg+8,+9
            float2 v3 = *(const float2*)(r1 + 32);   // row g+8
            ssq[2 * m]     += v0.x * v0.x + v0.y * v0.y + v2.x * v2.x + v2.y * v2.y;
            ssq[2 * m + 1] += v1.x * v1.x + v1.y * v1.y + v3.x * v3.x + v3.y * v3.y;
            uint32_t a0 = pack_bf16(v0.x, v0.y);
            uint32_t a1 = pack_bf16(v1.x, v1.y);
            uint32_t a2 = pack_bf16(v2.x, v2.y);
            uint32_t a3 = pack_bf16(v3.x, v3.y);
            #pragma unroll
            for (int j = 0; j < 8; ++j)
                mma_bf16(acc[m][j], a0, a1, a2, a3, b[j].x, b[j].y);
        }
    }

    // ---- finalize norms: reduce over the 4 quad (tg) lanes ----
    #pragma unroll
    for (int i = 0; i < 4; ++i) {
        ssq[i] += __shfl_xor_sync(0xffffffffu, ssq[i], 1);
        ssq[i] += __shfl_xor_sync(0xffffffffu, ssq[i], 2);
    }

    const float alphav = *alphap;
    float lossacc = 0.f;

    // ---- epilogue: per-row scale, softmax over 64 (quad-shfl), store, loss ----
    #pragma unroll
    for (int i = 0; i < 4; ++i) {      // row R = row0 + w*32 + i*8 + g
        const int m = i >> 1, hi = i & 1;
        float inv = 1.0f / fmaxf(sqrtf(ssq[i]), 1e-12f);
        float s[16];
        #pragma unroll
        for (int j = 0; j < 8; ++j) {
            s[2 * j]     = acc[m][j][hi * 2]     * inv;
            s[2 * j + 1] = acc[m][j][hi * 2 + 1] * inv;
        }
        float mx = -1e30f;
        #pragma unroll
        for (int j = 0; j < 16; ++j) mx = fmaxf(mx, s[j] * alphav);
        mx = fmaxf(mx, __shfl_xor_sync(0xffffffffu, mx, 1));
        mx = fmaxf(mx, __shfl_xor_sync(0xffffffffu, mx, 2));
        float e[16];
        float es = 0.f, ps = 0.f;
        #pragma unroll
        for (int j = 0; j < 16; ++j) {
            e[j] = __expf(s[j] * alphav - mx);
            es += e[j];
            ps += e[j] * s[j];
        }
        es += __shfl_xor_sync(0xffffffffu, es, 1);
        es += __shfl_xor_sync(0xffffffffu, es, 2);
        ps += __shfl_xor_sync(0xffffffffu, ps, 1);
        ps += __shfl_xor_sync(0xffffffffu, ps, 2);
        float rs = 1.0f / es;
        if (tg == 0) lossacc += ps * rs;
        if (store_probs) {
            size_t R = row0 + (size_t)w * 32 + i * 8 + g;
            float* ob = out + (size_t)loss_off + R * KDIM + tg * 2;
            #pragma unroll
            for (int j = 0; j < 8; ++j) {   // scalar: out may be 4B-misaligned by loss_off
                ob[j * 8]     = e[2 * j] * rs;
                ob[j * 8 + 1] = e[2 * j + 1] * rs;
            }
        }
    }

    // ---- deterministic per-block loss partial ----
    #pragma unroll
    for (int o = 16; o; o >>= 1) lossacc += __shfl_xor_sync(0xffffffffu, lossacc, o);
    float* wred = (float*)(smem + SM_WRED);
    if (lane == 0) wred[w] = lossacc;
    __syncthreads();
    if (t == 0) {
        float ssum = wred[0] + wred[1] + wred[2] + wred[3];
        g_partial[blockIdx.x] = ssum;
    }
}

// ---------------------------------------------------------------------------
// Kernel 3: deterministic loss finalize
// ---------------------------------------------------------------------------
__global__ void finalize_kernel(float* __restrict__ out, int nblocks, int N,
                                int write_loss) {
    if (!write_loss) return;
    __shared__ float sm[256];
    float s = 0.f;
    for (int i = threadIdx.x; i < nblocks; i += 256) s += g_partial[i];
    sm[threadIdx.x] = s;
    __syncthreads();
    for (int o = 128; o; o >>= 1) {
        if (threadIdx.x < o) sm[threadIdx.x] += sm[threadIdx.x + o];
        __syncthreads();
    }
    if (threadIdx.x == 0) out[0] = -sm[0] / (float)N;
}

// ---------------------------------------------------------------------------
extern "C" void kernel_launch(void* const* d_in, const int* in_sizes, int n_in,
                              void* d_out, int out_size) {
    const float* x        = (const float*)d_in[0];
    const float* clusters = (const float*)d_in[1];
    const float* alpha    = (const float*)d_in[2];
    float* out = (float*)d_out;

    int N = in_sizes[0] / DDIM;              // 131072
    int nblocks = N / TILE_ROWS;             // 1024

    // Output layout (confirmed): out[0]=loss, out[1:]=probs when size nk+1
    long long nk = (long long)N * KDIM;
    int loss_off = 0, store_probs = 1, write_loss = 0;
    if ((long long)out_size == nk + 1) { loss_off = 1; write_loss = 1; }
    else if ((long long)out_size == nk) { loss_off = 0; write_loss = 0; }
    else { store_probs = 0; write_loss = 1; }

    cudaFuncSetAttribute(cluster_mma_kernel,
                         cudaFuncAttributeMaxDynamicSharedMemorySize, SMEM_TOTAL);

    norm_clusters_kernel<<<KDIM, 128>>>(clusters);
    cluster_mma_kernel<<<nblocks, THREADS, SMEM_TOTAL>>>(x, alpha, out,
                                                         loss_off, store_probs);
    finalize_kernel<<<1, 256>>>(out, nblocks, N, write_loss);
}

// round 15
// speedup vs baseline: 3.3154x; 1.1528x over previous
#include <cuda_runtime.h>
#include <math.h>
#include <stdint.h>

// Fixed shapes: x[131072,512] f32, clusters[64,512] f32, alpha scalar
#define DDIM 512
#define KDIM 64
#define TILE_ROWS 128
#define KC 32                    // k elements per chunk = 128 B per row (2 k-steps)
#define NCH (DDIM / KC)          // 16 chunks
#define THREADS 128              // 4 warps; warp w owns rows w*32..w*32+31
#define APITCH 144               // bytes per A row in smem (32 floats + 16 pad)
#define ASTAGE (TILE_ROWS * APITCH)  // 18432 B
#define NSTAGE 2

// SMEM layout (bytes): 2 A stages + wred
#define SM_A    0
#define SM_WRED (NSTAGE * ASTAGE)          // 36864
#define SMEM_TOTAL (SM_WRED + 16)          // 36880

#define MAXBLK 8192
__device__ uint2 g_bfh[32 * 256];          // bf16 B fragments [ks16][j*32+lane]
__device__ float g_partial[MAXBLK];        // per-block loss partials

// ---- helpers ---------------------------------------------------------------
static __device__ __forceinline__ uint32_t smem_u32(const void* p) {
    uint32_t a;
    asm("{ .reg .u64 t; cvta.to.shared.u64 t, %1; cvt.u32.u64 %0, t; }"
        : "=r"(a) : "l"(p));
    return a;
}
static __device__ __forceinline__ void cp16(uint32_t saddr, const void* g) {
    asm volatile("cp.async.cg.shared.global [%0], [%1], 16;" :: "r"(saddr), "l"(g));
}
#define CP_COMMIT() asm volatile("cp.async.commit_group;" ::: "memory")
#define CP_WAIT1()  asm volatile("cp.async.wait_group 1;" ::: "memory")
#define CP_WAIT0()  asm volatile("cp.async.wait_group 0;" ::: "memory")

// pack two f32 -> bf16x2 (round-to-nearest-even; low half = first arg)
static __device__ __forceinline__ uint32_t pack_bf16(float lo, float hi) {
    uint32_t r;
    asm("cvt.rn.bf16x2.f32 %0, %1, %2;" : "=r"(r) : "f"(hi), "f"(lo));
    return r;
}

static __device__ __forceinline__ void mma_bf16(float* c,
                                                uint32_t a0, uint32_t a1,
                                                uint32_t a2, uint32_t a3,
                                                uint32_t b0, uint32_t b1) {
    asm volatile(
        "mma.sync.aligned.m16n8k16.row.col.f32.bf16.bf16.f32 "
        "{%0,%1,%2,%3}, {%4,%5,%6,%7}, {%8,%9}, {%0,%1,%2,%3};"
        : "+f"(c[0]), "+f"(c[1]), "+f"(c[2]), "+f"(c[3])
        : "r"(a0), "r"(a1), "r"(a2), "r"(a3), "r"(b0), "r"(b1));
}

// ---------------------------------------------------------------------------
// Kernel 1: L2-normalize clusters, emit bf16 B fragments (m16n8k16 col-major).
//   For kstep ks, col n = j*8 + (lane>>2), quad tg = lane&3:
//     b0 = {cn[n][ks*16+2tg], +1}, b1 = {+8, +9}.
// ---------------------------------------------------------------------------
__global__ void norm_clusters_kernel(const float* __restrict__ clusters) {
    int k = blockIdx.x;          // 64 blocks
    int t = threadIdx.x;         // 128 threads
    float4 v = ((const float4*)(clusters + (size_t)k * DDIM))[t];
    float ss = v.x * v.x + v.y * v.y + v.z * v.z + v.w * v.w;
    #pragma unroll
    for (int o = 16; o; o >>= 1) ss += __shfl_xor_sync(0xffffffffu, ss, o);
    __shared__ float ws[4];
    __shared__ float s_inv;
    __shared__ float sc[DDIM];
    if ((t & 31) == 0) ws[t >> 5] = ss;
    __syncthreads();
    if (t == 0) {
        float s = ws[0] + ws[1] + ws[2] + ws[3];
        s_inv = 1.0f / fmaxf(sqrtf(s), 1e-12f);
    }
    __syncthreads();
    float iv = s_inv;
    sc[t * 4 + 0] = v.x * iv;
    sc[t * 4 + 1] = v.y * iv;
    sc[t * 4 + 2] = v.z * iv;
    sc[t * 4 + 3] = v.w * iv;
    __syncthreads();
    {
        int ks = t >> 2, tg = t & 3;
        const float* s = sc + ks * 16 + tg * 2;
        uint2 b;
        b.x = pack_bf16(s[0], s[1]);
        b.y = pack_bf16(s[8], s[9]);
        g_bfh[ks * 256 + ((k >> 3) << 5) + ((k & 7) << 2) + tg] = b;
    }
}

// ---------------------------------------------------------------------------
// Kernel 2: bf16 m16n8k16 GEMM tile 128x64 + fused normalize/softmax/loss.
// Warp w owns rows w*32..w*32+31, loads them itself with fully coalesced
// cp.async (4 full 128B lines per instruction). 2-stage warp-private
// pipeline, no block barriers. 4 CTAs/SM.
// ---------------------------------------------------------------------------
__global__ __launch_bounds__(THREADS, 4)
void cluster_mma_kernel(const float* __restrict__ x,
                        const float* __restrict__ alphap,
                        float* __restrict__ out,
                        int loss_off, int store_probs) {
    extern __shared__ char smem[];
    const uint32_t sb = smem_u32(smem);
    const int t = threadIdx.x;
    const int w = t >> 5, lane = t & 31;
    const int g = lane >> 2, tg = lane & 3;
    const size_t row0 = (size_t)blockIdx.x * TILE_ROWS;

    // Coalesced A loader: lane -> (arow = lane>>3, aseg = lane&7).
    // Instruction q (0..7): row = w*32 + q*4 + arow, bytes aseg*16 of the
    // 128B chunk. 4 rows x 128 B contiguous per instruction = 4 lines.
    const int arow = lane >> 3, aseg = lane & 7;
    const float* xb = x + (row0 + w * 32 + arow) * DDIM + aseg * 4;
    const uint32_t sbA = sb + SM_A + (w * 32 + arow) * APITCH + aseg * 16;

    // ---- prologue: issue chunk 0 ----
    {
        const float* src = xb;                 // chunk 0: k offset 0
        #pragma unroll
        for (int q = 0; q < 8; ++q)
            cp16(sbA + q * 4 * APITCH, src + (size_t)q * 4 * DDIM);
        CP_COMMIT();
    }

    float acc[2][8][4];
    #pragma unroll
    for (int m = 0; m < 2; ++m)
        #pragma unroll
        for (int j = 0; j < 8; ++j)
            #pragma unroll
            for (int r = 0; r < 4; ++r) acc[m][j][r] = 0.f;
    float ssq[4] = {0.f, 0.f, 0.f, 0.f};

    // ---- mainloop: warp-private 2-stage pipeline ----
    for (int c = 0; c < NCH; ++c) {
        // B fragments for kstep 2c (L1-resident; overlaps the wait)
        uint2 b[8];
        {
            const uint2* bp = g_bfh + (2 * c) * 256 + lane;
            #pragma unroll
            for (int j = 0; j < 8; ++j) b[j] = __ldg(bp + j * 32);
        }

        if (c + 1 < NCH) {          // issue chunk c+1 into the other stage
            const float* src = xb + (c + 1) * KC;
            uint32_t ab = sbA + ((c + 1) & 1) * ASTAGE;
            #pragma unroll
            for (int q = 0; q < 8; ++q)
                cp16(ab + q * 4 * APITCH, src + (size_t)q * 4 * DDIM);
            CP_COMMIT();
            CP_WAIT1();             // chunk c landed; c+1 stays in flight
        } else {
            CP_WAIT0();             // final chunk
        }
        __syncwarp();

        const char* ap = smem + SM_A + (c & 1) * ASTAGE;

        #pragma unroll
        for (int u = 0; u < 2; ++u) {
            if (u == 1) {           // B fragments for kstep 2c+1
                const uint2* bp = g_bfh + (2 * c + 1) * 256 + lane;
                #pragma unroll
                for (int j = 0; j < 8; ++j) b[j] = __ldg(bp + j * 32);
            }
            #pragma unroll
            for (int m = 0; m < 2; ++m) {
                const char* r0 = ap + (w * 32 + m * 16 + g) * APITCH + u * 64 + tg * 8;
                const char* r1 = r0 + 8 * APITCH;
                float2 v0 = *(const float2*)(r0);        // row g,   k=2tg,2tg+1
                float2 v1 = *(const float2*)(r1);        // row g+8
                float2 v2 = *(const float2*)(r0 + 32);   // row g,   k=+8,+9
                float2 v3 = *(const float2*)(r1 + 32);   // row g+8
                ssq[2 * m]     += v0.x * v0.x + v0.y * v0.y + v2.x * v2.x + v2.y * v2.y;
                ssq[2 * m + 1] += v1.x * v1.x + v1.y * v1.y + v3.x * v3.x + v3.y * v3.y;
                uint32_t a0 = pack_bf16(v0.x, v0.y);
                uint32_t a1 = pack_bf16(v1.x, v1.y);
                uint32_t a2 = pack_bf16(v2.x, v2.y);
                uint32_t a3 = pack_bf16(v3.x, v3.y);
                #pragma unroll
                for (int j = 0; j < 8; ++j)
                    mma_bf16(acc[m][j], a0, a1, a2, a3, b[j].x, b[j].y);
            }
        }
    }

    // ---- finalize norms: reduce over the 4 quad (tg) lanes ----
    #pragma unroll
    for (int i = 0; i < 4; ++i) {
        ssq[i] += __shfl_xor_sync(0xffffffffu, ssq[i], 1);
        ssq[i] += __shfl_xor_sync(0xffffffffu, ssq[i], 2);
    }

    const float alphav = *alphap;
    float lossacc = 0.f;

    // ---- epilogue: per-row scale, softmax over 64 (quad-shfl), store, loss ----
    #pragma unroll
    for (int i = 0; i < 4; ++i) {      // row R = row0 + w*32 + i*8 + g
        const int m = i >> 1, hi = i & 1;
        float inv = 1.0f / fmaxf(sqrtf(ssq[i]), 1e-12f);
        float s[16];
        #pragma unroll
        for (int j = 0; j < 8; ++j) {
            s[2 * j]     = acc[m][j][hi * 2]     * inv;
            s[2 * j + 1] = acc[m][j][hi * 2 + 1] * inv;
        }
        float mx = -1e30f;
        #pragma unroll
        for (int j = 0; j < 16; ++j) mx = fmaxf(mx, s[j] * alphav);
        mx = fmaxf(mx, __shfl_xor_sync(0xffffffffu, mx, 1));
        mx = fmaxf(mx, __shfl_xor_sync(0xffffffffu, mx, 2));
        float e[16];
        float es = 0.f, ps = 0.f;
        #pragma unroll
        for (int j = 0; j < 16; ++j) {
            e[j] = __expf(s[j] * alphav - mx);
            es += e[j];
            ps += e[j] * s[j];
        }
        es += __shfl_xor_sync(0xffffffffu, es, 1);
        es += __shfl_xor_sync(0xffffffffu, es, 2);
        ps += __shfl_xor_sync(0xffffffffu, ps, 1);
        ps += __shfl_xor_sync(0xffffffffu, ps, 2);
        float rs = 1.0f / es;
        if (tg == 0) lossacc += ps * rs;
        if (store_probs) {
            size_t R = row0 + (size_t)w * 32 + i * 8 + g;
            float* ob = out + (size_t)loss_off + R * KDIM + tg * 2;
            #pragma unroll
            for (int j = 0; j < 8; ++j) {   // scalar: out may be 4B-misaligned by loss_off
                ob[j * 8]     = e[2 * j] * rs;
                ob[j * 8 + 1] = e[2 * j + 1] * rs;
            }
        }
    }

    // ---- deterministic per-block loss partial ----
    #pragma unroll
    for (int o = 16; o; o >>= 1) lossacc += __shfl_xor_sync(0xffffffffu, lossacc, o);
    float* wred = (float*)(smem + SM_WRED);
    if (lane == 0) wred[w] = lossacc;
    __syncthreads();
    if (t == 0) {
        float ssum = wred[0] + wred[1] + wred[2] + wred[3];
        g_partial[blockIdx.x] = ssum;
    }
}

// ---------------------------------------------------------------------------
// Kernel 3: deterministic loss finalize
// ---------------------------------------------------------------------------
__global__ void finalize_kernel(float* __restrict__ out, int nblocks, int N,
                                int write_loss) {
    if (!write_loss) return;
    __shared__ float sm[256];
    float s = 0.f;
    for (int i = threadIdx.x; i < nblocks; i += 256) s += g_partial[i];
    sm[threadIdx.x] = s;
    __syncthreads();
    for (int o = 128; o; o >>= 1) {
        if (threadIdx.x < o) sm[threadIdx.x] += sm[threadIdx.x + o];
        __syncthreads();
    }
    if (threadIdx.x == 0) out[0] = -sm[0] / (float)N;
}

// ---------------------------------------------------------------------------
extern "C" void kernel_launch(void* const* d_in, const int* in_sizes, int n_in,
                              void* d_out, int out_size) {
    const float* x        = (const float*)d_in[0];
    const float* clusters = (const float*)d_in[1];
    const float* alpha    = (const float*)d_in[2];
    float* out = (float*)d_out;

    int N = in_sizes[0] / DDIM;              // 131072
    int nblocks = N / TILE_ROWS;             // 1024

    // Output layout (confirmed): out[0]=loss, out[1:]=probs when size nk+1
    long long nk = (long long)N * KDIM;
    int loss_off = 0, store_probs = 1, write_loss = 0;
    if ((long long)out_size == nk + 1) { loss_off = 1; write_loss = 1; }
    else if ((long long)out_size == nk) { loss_off = 0; write_loss = 0; }
    else { store_probs = 0; write_loss = 1; }

    cudaFuncSetAttribute(cluster_mma_kernel,
                         cudaFuncAttributeMaxDynamicSharedMemorySize, SMEM_TOTAL);

    norm_clusters_kernel<<<KDIM, 128>>>(clusters);
    cluster_mma_kernel<<<nblocks, THREADS, SMEM_TOTAL>>>(x, alpha, out,
                                                         loss_off, store_probs);
    finalize_kernel<<<1, 256>>>(out, nblocks, N, write_loss);
}

// round 16
// speedup vs baseline: 3.4128x; 1.0294x over previous
#include <cuda_runtime.h>
#include <math.h>
#include <stdint.h>

// Fixed shapes: x[131072,512] f32, clusters[64,512] f32, alpha scalar
#define DDIM 512
#define KDIM 64
#define TILE_ROWS 128
#define KC 32                    // k elements per chunk = 128 B per row (2 k-steps)
#define NCH (DDIM / KC)          // 16 chunks
#define THREADS 128              // 4 warps; warp w owns rows w*32..w*32+31
#define APITCH 144               // bytes per A row in smem (32 floats + 16 pad)
#define ASTAGE (TILE_ROWS * APITCH)  // 18432 B
#define NSTAGE 2

// SMEM layout (bytes): 2 A stages (reused as 32KB probs stage) + wred
#define SM_A    0
#define SM_WRED (NSTAGE * ASTAGE)          // 36864
#define SMEM_TOTAL (SM_WRED + 16)          // 36880

#define MAXBLK 8192
__device__ uint2 g_bfh[32 * 256];          // bf16 B fragments [ks16][j*32+lane]
__device__ float g_partial[MAXBLK];        // per-block loss partials

// ---- helpers ---------------------------------------------------------------
static __device__ __forceinline__ uint32_t smem_u32(const void* p) {
    uint32_t a;
    asm("{ .reg .u64 t; cvta.to.shared.u64 t, %1; cvt.u32.u64 %0, t; }"
        : "=r"(a) : "l"(p));
    return a;
}
static __device__ __forceinline__ void cp16(uint32_t saddr, const void* g) {
    asm volatile("cp.async.cg.shared.global [%0], [%1], 16;" :: "r"(saddr), "l"(g));
}
#define CP_COMMIT() asm volatile("cp.async.commit_group;" ::: "memory")
#define CP_WAIT1()  asm volatile("cp.async.wait_group 1;" ::: "memory")
#define CP_WAIT0()  asm volatile("cp.async.wait_group 0;" ::: "memory")

// pack two f32 -> bf16x2 (round-to-nearest-even; low half = first arg)
static __device__ __forceinline__ uint32_t pack_bf16(float lo, float hi) {
    uint32_t r;
    asm("cvt.rn.bf16x2.f32 %0, %1, %2;" : "=r"(r) : "f"(hi), "f"(lo));
    return r;
}

static __device__ __forceinline__ void mma_bf16(float* c,
                                                uint32_t a0, uint32_t a1,
                                                uint32_t a2, uint32_t a3,
                                                uint32_t b0, uint32_t b1) {
    asm volatile(
        "mma.sync.aligned.m16n8k16.row.col.f32.bf16.bf16.f32 "
        "{%0,%1,%2,%3}, {%4,%5,%6,%7}, {%8,%9}, {%0,%1,%2,%3};"
        : "+f"(c[0]), "+f"(c[1]), "+f"(c[2]), "+f"(c[3])
        : "r"(a0), "r"(a1), "r"(a2), "r"(a3), "r"(b0), "r"(b1));
}

// ---------------------------------------------------------------------------
// Kernel 1: L2-normalize clusters, emit bf16 B fragments (m16n8k16 col-major).
// ---------------------------------------------------------------------------
__global__ void norm_clusters_kernel(const float* __restrict__ clusters) {
    int k = blockIdx.x;          // 64 blocks
    int t = threadIdx.x;         // 128 threads
    float4 v = ((const float4*)(clusters + (size_t)k * DDIM))[t];
    float ss = v.x * v.x + v.y * v.y + v.z * v.z + v.w * v.w;
    #pragma unroll
    for (int o = 16; o; o >>= 1) ss += __shfl_xor_sync(0xffffffffu, ss, o);
    __shared__ float ws[4];
    __shared__ float s_inv;
    __shared__ float sc[DDIM];
    if ((t & 31) == 0) ws[t >> 5] = ss;
    __syncthreads();
    if (t == 0) {
        float s = ws[0] + ws[1] + ws[2] + ws[3];
        s_inv = 1.0f / fmaxf(sqrtf(s), 1e-12f);
    }
    __syncthreads();
    float iv = s_inv;
    sc[t * 4 + 0] = v.x * iv;
    sc[t * 4 + 1] = v.y * iv;
    sc[t * 4 + 2] = v.z * iv;
    sc[t * 4 + 3] = v.w * iv;
    __syncthreads();
    {
        int ks = t >> 2, tg = t & 3;
        const float* s = sc + ks * 16 + tg * 2;
        uint2 b;
        b.x = pack_bf16(s[0], s[1]);
        b.y = pack_bf16(s[8], s[9]);
        g_bfh[ks * 256 + ((k >> 3) << 5) + ((k & 7) << 2) + tg] = b;
    }
}

// ---------------------------------------------------------------------------
// Kernel 2: bf16 m16n8k16 GEMM tile 128x64 + fused normalize/softmax/loss.
// Warp-private coalesced cp.async A pipeline (2 stages); probs staged in
// smem and streamed out with aligned float4 stores. 4 CTAs/SM.
// ---------------------------------------------------------------------------
__global__ __launch_bounds__(THREADS, 4)
void cluster_mma_kernel(const float* __restrict__ x,
                        const float* __restrict__ alphap,
                        float* __restrict__ out,
                        int loss_off, int store_probs) {
    extern __shared__ char smem[];
    const uint32_t sb = smem_u32(smem);
    const int t = threadIdx.x;
    const int w = t >> 5, lane = t & 31;
    const int g = lane >> 2, tg = lane & 3;
    const size_t row0 = (size_t)blockIdx.x * TILE_ROWS;

    // Coalesced A loader: lane -> (arow = lane>>3, aseg = lane&7).
    const int arow = lane >> 3, aseg = lane & 7;
    const float* xb = x + (row0 + w * 32 + arow) * DDIM + aseg * 4;
    const uint32_t sbA = sb + SM_A + (w * 32 + arow) * APITCH + aseg * 16;

    // ---- prologue: issue chunk 0 ----
    {
        const float* src = xb;
        #pragma unroll
        for (int q = 0; q < 8; ++q)
            cp16(sbA + q * 4 * APITCH, src + (size_t)q * 4 * DDIM);
        CP_COMMIT();
    }

    float acc[2][8][4];
    #pragma unroll
    for (int m = 0; m < 2; ++m)
        #pragma unroll
        for (int j = 0; j < 8; ++j)
            #pragma unroll
            for (int r = 0; r < 4; ++r) acc[m][j][r] = 0.f;
    float ssq[4] = {0.f, 0.f, 0.f, 0.f};

    // ---- mainloop: warp-private 2-stage pipeline ----
    for (int c = 0; c < NCH; ++c) {
        uint2 b[8];
        {
            const uint2* bp = g_bfh + (2 * c) * 256 + lane;
            #pragma unroll
            for (int j = 0; j < 8; ++j) b[j] = __ldg(bp + j * 32);
        }

        if (c + 1 < NCH) {
            const float* src = xb + (c + 1) * KC;
            uint32_t ab = sbA + ((c + 1) & 1) * ASTAGE;
            #pragma unroll
            for (int q = 0; q < 8; ++q)
                cp16(ab + q * 4 * APITCH, src + (size_t)q * 4 * DDIM);
            CP_COMMIT();
            CP_WAIT1();
        } else {
            CP_WAIT0();
        }
        __syncwarp();

        const char* ap = smem + SM_A + (c & 1) * ASTAGE;

        #pragma unroll
        for (int u = 0; u < 2; ++u) {
            if (u == 1) {
                const uint2* bp = g_bfh + (2 * c + 1) * 256 + lane;
                #pragma unroll
                for (int j = 0; j < 8; ++j) b[j] = __ldg(bp + j * 32);
            }
            #pragma unroll
            for (int m = 0; m < 2; ++m) {
                const char* r0 = ap + (w * 32 + m * 16 + g) * APITCH + u * 64 + tg * 8;
                const char* r1 = r0 + 8 * APITCH;
                float2 v0 = *(const float2*)(r0);
                float2 v1 = *(const float2*)(r1);
                float2 v2 = *(const float2*)(r0 + 32);
                float2 v3 = *(const float2*)(r1 + 32);
                ssq[2 * m]     += v0.x * v0.x + v0.y * v0.y + v2.x * v2.x + v2.y * v2.y;
                ssq[2 * m + 1] += v1.x * v1.x + v1.y * v1.y + v3.x * v3.x + v3.y * v3.y;
                uint32_t a0 = pack_bf16(v0.x, v0.y);
                uint32_t a1 = pack_bf16(v1.x, v1.y);
                uint32_t a2 = pack_bf16(v2.x, v2.y);
                uint32_t a3 = pack_bf16(v3.x, v3.y);
                #pragma unroll
                for (int j = 0; j < 8; ++j)
                    mma_bf16(acc[m][j], a0, a1, a2, a3, b[j].x, b[j].y);
            }
        }
    }

    // ---- finalize norms: reduce over the 4 quad (tg) lanes ----
    #pragma unroll
    for (int i = 0; i < 4; ++i) {
        ssq[i] += __shfl_xor_sync(0xffffffffu, ssq[i], 1);
        ssq[i] += __shfl_xor_sync(0xffffffffu, ssq[i], 2);
    }

    const float alphav = *alphap;
    float lossacc = 0.f;

    // Probs stage: smem region aligned mod 16 to the global destination so the
    // copy-out can use aligned float4 on both sides despite the +loss_off shift.
    float* gdst = out + (size_t)loss_off + row0 * KDIM;
    char* sstage = smem + SM_A + (int)((size_t)gdst & 12);

    if (store_probs) __syncthreads();   // all warps done reading A stages

    // ---- epilogue: per-row scale, softmax over 64 (quad-shfl), stage, loss ----
    #pragma unroll
    for (int i = 0; i < 4; ++i) {      // local row lrow = w*32 + i*8 + g
        const int m = i >> 1, hi = i & 1;
        float inv = 1.0f / fmaxf(sqrtf(ssq[i]), 1e-12f);
        float s[16];
        #pragma unroll
        for (int j = 0; j < 8; ++j) {
            s[2 * j]     = acc[m][j][hi * 2]     * inv;
            s[2 * j + 1] = acc[m][j][hi * 2 + 1] * inv;
        }
        float mx = -1e30f;
        #pragma unroll
        for (int j = 0; j < 16; ++j) mx = fmaxf(mx, s[j] * alphav);
        mx = fmaxf(mx, __shfl_xor_sync(0xffffffffu, mx, 1));
        mx = fmaxf(mx, __shfl_xor_sync(0xffffffffu, mx, 2));
        float e[16];
        float es = 0.f, ps = 0.f;
        #pragma unroll
        for (int j = 0; j < 16; ++j) {
            e[j] = __expf(s[j] * alphav - mx);
            es += e[j];
            ps += e[j] * s[j];
        }
        es += __shfl_xor_sync(0xffffffffu, es, 1);
        es += __shfl_xor_sync(0xffffffffu, es, 2);
        ps += __shfl_xor_sync(0xffffffffu, ps, 1);
        ps += __shfl_xor_sync(0xffffffffu, ps, 2);
        float rs = 1.0f / es;
        if (tg == 0) lossacc += ps * rs;
        if (store_probs) {
            int lrow = w * 32 + i * 8 + g;
            float* sb_row = (float*)(sstage) + lrow * KDIM + tg * 2;
            #pragma unroll
            for (int j = 0; j < 8; ++j) {
                sb_row[j * 8]     = e[2 * j] * rs;
                sb_row[j * 8 + 1] = e[2 * j + 1] * rs;
            }
        }
    }

    // ---- cooperative aligned copy-out of the staged probs tile ----
    if (store_probs) {
        __syncthreads();                // stage complete
        const int total_f = TILE_ROWS * KDIM;                 // 8192 floats
        const int head_f = (int)(((16 - ((size_t)gdst & 15)) & 15) >> 2);
        for (int i = t; i < head_f; i += THREADS)
            gdst[i] = *(const float*)(sstage + (size_t)i * 4);
        const int nf4 = (total_f - head_f) >> 2;
        const float4* s4 = (const float4*)(sstage + (size_t)head_f * 4);
        float4* g4 = (float4*)(gdst + head_f);
        for (int q = t; q < nf4; q += THREADS) g4[q] = s4[q];
        const int done = head_f + nf4 * 4;
        for (int i = done + t; i < total_f; i += THREADS)
            gdst[i] = *(const float*)(sstage + (size_t)i * 4);
    }

    // ---- deterministic per-block loss partial ----
    #pragma unroll
    for (int o = 16; o; o >>= 1) lossacc += __shfl_xor_sync(0xffffffffu, lossacc, o);
    float* wred = (float*)(smem + SM_WRED);
    if (lane == 0) wred[w] = lossacc;
    __syncthreads();
    if (t == 0) {
        float ssum = wred[0] + wred[1] + wred[2] + wred[3];
        g_partial[blockIdx.x] = ssum;
    }
}

// ---------------------------------------------------------------------------
// Kernel 3: deterministic loss finalize
// ---------------------------------------------------------------------------
__global__ void finalize_kernel(float* __restrict__ out, int nblocks, int N,
                                int write_loss) {
    if (!write_loss) return;
    __shared__ float sm[256];
    float s = 0.f;
    for (int i = threadIdx.x; i < nblocks; i += 256) s += g_partial[i];
    sm[threadIdx.x] = s;
    __syncthreads();
    for (int o = 128; o; o >>= 1) {
        if (threadIdx.x < o) sm[threadIdx.x] += sm[threadIdx.x + o];
        __syncthreads();
    }
    if (threadIdx.x == 0) out[0] = -sm[0] / (float)N;
}

// ---------------------------------------------------------------------------
extern "C" void kernel_launch(void* const* d_in, const int* in_sizes, int n_in,
                              void* d_out, int out_size) {
    const float* x        = (const float*)d_in[0];
    const float* clusters = (const float*)d_in[1];
    const float* alpha    = (const float*)d_in[2];
    float* out = (float*)d_out;

    int N = in_sizes[0] / DDIM;              // 131072
    int nblocks = N / TILE_ROWS;             // 1024

    // Output layout (confirmed): out[0]=loss, out[1:]=probs when size nk+1
    long long nk = (long long)N * KDIM;
    int loss_off = 0, store_probs = 1, write_loss = 0;
    if ((long long)out_size == nk + 1) { loss_off = 1; write_loss = 1; }
    else if ((long long)out_size == nk) { loss_off = 0; write_loss = 0; }
    else { store_probs = 0; write_loss = 1; }

    cudaFuncSetAttribute(cluster_mma_kernel,
                         cudaFuncAttributeMaxDynamicSharedMemorySize, SMEM_TOTAL);

    norm_clusters_kernel<<<KDIM, 128>>>(clusters);
    cluster_mma_kernel<<<nblocks, THREADS, SMEM_TOTAL>>>(x, alpha, out,
                                                         loss_off, store_probs);
    finalize_kernel<<<1, 256>>>(out, nblocks, N, write_loss);
}